// round 9
// baseline (speedup 1.0000x reference)
#include <cuda_runtime.h>
#include <cuda_fp16.h>
#include <cstdint>

#define DDIM 768
#define KCB  2048
#define NTOK 16384
#define BM   128
#define BN   128
#define BK   32
#define NKIT (DDIM / BK)        // 24 k-iters per N-block
#define NNB  (KCB / BN)         // 16 N-blocks
#define TOTIT (NKIT * NNB)      // 384
#define MARGIN 0.20f
#define CAP 4096
#define NT 256                  // threads in vq_main (8 warps, 2x4 grid)

#define A_BYTES (NKIT * 8192)   // 196608
#define B_BYTES (4 * 8192)      // 4-stage B ring
#define SMEM_TOTAL (A_BYTES + B_BYTES)   // 229376

// rescue tiling
#define RG  16
#define RNB 16
#define XS_STRIDE 769
#define CT_STRIDE 132
#define RSMEM ((RG * XS_STRIDE + 32 * CT_STRIDE) * 4)   // 66112

#define FIXG 8                  // slots per fixup block

// ---------------- device scratch ----------------
__device__ __half g_cb_h[KCB * DDIM];
__device__ float g_half_esq[KCB];
__device__ int   g_indices[NTOK];
__device__ float g_row_partial[NTOK];
__device__ int   g_flag_count;
__device__ int   g_flag_rows[CAP];
__device__ float g_seg_val[CAP][RNB];
__device__ int   g_seg_idx[CAP][RNB];

// ---------------- helpers ----------------
__device__ __forceinline__ uint32_t smem_u32(const void* p) {
    uint32_t a;
    asm("{ .reg .u64 t; cvta.to.shared.u64 t, %1; cvt.u32.u64 %0, t; }"
        : "=r"(a) : "l"(p));
    return a;
}
#define CP_ASYNC16(dst, src) \
    asm volatile("cp.async.cg.shared.global [%0], [%1], 16;" :: "r"(dst), "l"(src))
#define CP_COMMIT() asm volatile("cp.async.commit_group;" ::: "memory")
#define CP_WAIT0()  asm volatile("cp.async.wait_group 0;" ::: "memory")
#define CP_WAIT2()  asm volatile("cp.async.wait_group 2;" ::: "memory")

__device__ __forceinline__ int swz16(int r, int c) {
    return (r >> 1) * 8 + ((((r & 1) << 2) | c) ^ ((r >> 1) & 7));
}
__device__ __forceinline__ void ldsm4(uint32_t* r, uint32_t addr) {
    asm volatile("ldmatrix.sync.aligned.m8n8.x4.shared.b16 {%0,%1,%2,%3}, [%4];"
                 : "=r"(r[0]), "=r"(r[1]), "=r"(r[2]), "=r"(r[3]) : "r"(addr));
}
__device__ __forceinline__ void mma16816(float* d, const uint32_t* a,
                                         uint32_t b0, uint32_t b1) {
    asm volatile(
        "mma.sync.aligned.m16n8k16.row.col.f32.f16.f16.f32 "
        "{%0,%1,%2,%3},{%4,%5,%6,%7},{%8,%9},{%0,%1,%2,%3};"
        : "+f"(d[0]), "+f"(d[1]), "+f"(d[2]), "+f"(d[3])
        : "r"(a[0]), "r"(a[1]), "r"(a[2]), "r"(a[3]), "r"(b0), "r"(b1));
}
__device__ __forceinline__ void merge2(float& b1, int& i1, float& b2,
                                       float ob1, int oi1, float ob2) {
    if (ob1 > b1 || (ob1 == b1 && oi1 < i1)) {
        b2 = fmaxf(b1, ob2); b1 = ob1; i1 = oi1;
    } else {
        b2 = fmaxf(b2, ob1);
    }
}

__device__ __forceinline__ void load_frags(
    uint32_t (&af)[4][4], uint32_t (&bf)[2][4],
    uint32_t Ab, uint32_t Bb, int c0,
    int warp_m, int warp_n, int a_r, int a_c, int b_r, int b_c)
{
    #pragma unroll
    for (int mt = 0; mt < 4; ++mt)
        ldsm4(af[mt], Ab + swz16(warp_m * 64 + mt * 16 + a_r, c0 + a_c) * 16);
    #pragma unroll
    for (int np = 0; np < 2; ++np)
        ldsm4(bf[np], Bb + swz16(warp_n * 32 + np * 16 + b_r, c0 + b_c) * 16);
}

// ---------------------------------------------------------------------------
// esq + codebook fp16 conversion + flag-counter reset (single launch)
// ---------------------------------------------------------------------------
__global__ void esq_kernel(const float* __restrict__ cbp) {
    if (blockIdx.x == 0 && threadIdx.x == 0) g_flag_count = 0;
    int k = blockIdx.x;
    const float* row = cbp + (size_t)k * DDIM;
    float s = 0.f;
    for (int d = threadIdx.x; d < DDIM; d += 256) {
        float v = row[d];
        s += v * v;
        g_cb_h[(size_t)k * DDIM + d] = __float2half(v);
    }
    #pragma unroll
    for (int off = 16; off > 0; off >>= 1) s += __shfl_down_sync(0xFFFFFFFFu, s, off);
    __shared__ float ws[8];
    if ((threadIdx.x & 31) == 0) ws[threadIdx.x >> 5] = s;
    __syncthreads();
    if (threadIdx.x == 0) {
        float t = 0.f;
        #pragma unroll
        for (int w = 0; w < 8; w++) t += ws[w];
        g_half_esq[k] = 0.5f * t;
    }
}

// ---------------------------------------------------------------------------
// Main fp16 mma.sync GEMM + argmax + FUSED gather/loss epilogue (as R8).
// ---------------------------------------------------------------------------
__global__ __launch_bounds__(NT, 1) void vq_main_kernel(
    const float* __restrict__ tokf, const __half* __restrict__ cbh,
    const float* __restrict__ cbf, float* __restrict__ outp, int write_indices)
{
    extern __shared__ char sm[];
    char* smA = sm;
    char* smB = sm + A_BYTES;

    const int tid = threadIdx.x;
    const int lane = tid & 31;
    const int wid = tid >> 5;
    const int warp_m = wid & 1;
    const int warp_n = wid >> 1;
    const int rowBase = blockIdx.x * BM;

    const uint32_t smA32 = smem_u32(smA);
    const uint32_t smB32 = smem_u32(smB);

    const int ld_r0 = tid >> 2, ld_c0 = tid & 3;
    const int ld_r1 = ld_r0 + 64;

    CP_ASYNC16(smB32 + swz16(ld_r0, ld_c0) * 16,
               cbh + (size_t)ld_r0 * DDIM + ld_c0 * 8);
    CP_ASYNC16(smB32 + swz16(ld_r1, ld_c0) * 16,
               cbh + (size_t)ld_r1 * DDIM + ld_c0 * 8);
    CP_COMMIT();
    CP_ASYNC16(smB32 + 8192 + swz16(ld_r0, ld_c0) * 16,
               cbh + (size_t)ld_r0 * DDIM + BK + ld_c0 * 8);
    CP_ASYNC16(smB32 + 8192 + swz16(ld_r1, ld_c0) * 16,
               cbh + (size_t)ld_r1 * DDIM + BK + ld_c0 * 8);
    CP_COMMIT();

    #pragma unroll 4
    for (int j = 0; j < 48; ++j) {
        int idx = tid + j * NT;
        int stage = idx >> 9;
        int within = idx & 511;
        int r = within >> 2, c2 = within & 3;
        const float* src = tokf + (size_t)(rowBase + r) * DDIM + stage * BK + c2 * 8;
        float4 a = *(const float4*)(src);
        float4 b = *(const float4*)(src + 4);
        __half2 h0 = __floats2half2_rn(a.x, a.y);
        __half2 h1 = __floats2half2_rn(a.z, a.w);
        __half2 h2 = __floats2half2_rn(b.x, b.y);
        __half2 h3 = __floats2half2_rn(b.z, b.w);
        uint4 o{*(uint32_t*)&h0, *(uint32_t*)&h1, *(uint32_t*)&h2, *(uint32_t*)&h3};
        *(uint4*)(smA + stage * 8192 + swz16(r, c2) * 16) = o;
    }

    float acc[4][4][4];
    #pragma unroll
    for (int mt = 0; mt < 4; ++mt)
        #pragma unroll
        for (int nt = 0; nt < 4; ++nt)
            #pragma unroll
            for (int e = 0; e < 4; ++e) acc[mt][nt][e] = 0.f;

    float tb1[8], tb2[8]; int ti1[8];
    #pragma unroll
    for (int s = 0; s < 8; ++s) { tb1[s] = -3.4e38f; tb2[s] = -3.4e38f; ti1[s] = 0x7FFFFFFF; }

    const int a_r = (lane & 15);
    const int a_c = (lane >> 4);
    const int b_r = ((lane >> 4) << 3) + (lane & 7);
    const int b_c = ((lane >> 3) & 1);

    uint32_t af[2][4][4];
    uint32_t bf[2][2][4];

    for (int ss = 0; ss < TOTIT / 2; ++ss) {
        __syncthreads();

        const int st0 = 2 * ss + 2;
        if (st0 < TOTIT) {
            #pragma unroll
            for (int j = 0; j < 2; ++j) {
                int st = st0 + j;
                int nb = st / NKIT, it = st % NKIT;
                const __half* base = cbh + (size_t)(nb * BN) * DDIM + it * BK + ld_c0 * 8;
                uint32_t dst = smB32 + (st & 3) * 8192;
                CP_ASYNC16(dst + swz16(ld_r0, ld_c0) * 16, base + (size_t)ld_r0 * DDIM);
                CP_ASYNC16(dst + swz16(ld_r1, ld_c0) * 16, base + (size_t)ld_r1 * DDIM);
                CP_COMMIT();
            }
            CP_WAIT2();
        } else {
            CP_WAIT0();
        }

        const int g0 = 2 * ss;
        const uint32_t Ab0 = smA32 + (g0 % NKIT) * 8192;
        const uint32_t Ab1 = smA32 + ((g0 + 1) % NKIT) * 8192;
        const uint32_t Bb0 = smB32 + (g0 & 3) * 8192;
        const uint32_t Bb1 = smB32 + ((g0 + 1) & 3) * 8192;

        load_frags(af[0], bf[0], Ab0, Bb0, 0, warp_m, warp_n, a_r, a_c, b_r, b_c);
        #pragma unroll
        for (int p = 0; p < 4; ++p) {
            const int cur = p & 1, nxt = cur ^ 1;
            if (p < 3) {
                const int pn = p + 1;
                load_frags(af[nxt], bf[nxt],
                           (pn >> 1) ? Ab1 : Ab0, (pn >> 1) ? Bb1 : Bb0,
                           (pn & 1) * 2, warp_m, warp_n, a_r, a_c, b_r, b_c);
            }
            #pragma unroll
            for (int mt = 0; mt < 4; ++mt)
                #pragma unroll
                for (int nt = 0; nt < 4; ++nt)
                    mma16816(acc[mt][nt], af[cur][mt],
                             bf[cur][nt >> 1][(nt & 1) * 2],
                             bf[cur][nt >> 1][(nt & 1) * 2 + 1]);
        }

        if (((g0 + 1) % NKIT) == NKIT - 1) {
            const int nbase = ((g0 + 1) / NKIT) * BN + warp_n * 32;
            #pragma unroll
            for (int mt = 0; mt < 4; ++mt) {
                #pragma unroll
                for (int nt = 0; nt < 4; ++nt) {
                    const int col0 = nbase + nt * 8 + (lane & 3) * 2;
                    const float he0 = __ldg(&g_half_esq[col0]);
                    const float he1 = __ldg(&g_half_esq[col0 + 1]);
                    float s0 = acc[mt][nt][0] - he0;
                    float s1 = acc[mt][nt][1] - he1;
                    float s2 = acc[mt][nt][2] - he0;
                    float s3 = acc[mt][nt][3] - he1;
                    const int s_lo = mt * 2, s_hi = mt * 2 + 1;
                    if (s0 > tb1[s_lo]) { tb2[s_lo] = tb1[s_lo]; tb1[s_lo] = s0; ti1[s_lo] = col0; }
                    else if (s0 > tb2[s_lo]) tb2[s_lo] = s0;
                    if (s1 > tb1[s_lo]) { tb2[s_lo] = tb1[s_lo]; tb1[s_lo] = s1; ti1[s_lo] = col0 + 1; }
                    else if (s1 > tb2[s_lo]) tb2[s_lo] = s1;
                    if (s2 > tb1[s_hi]) { tb2[s_hi] = tb1[s_hi]; tb1[s_hi] = s2; ti1[s_hi] = col0; }
                    else if (s2 > tb2[s_hi]) tb2[s_hi] = s2;
                    if (s3 > tb1[s_hi]) { tb2[s_hi] = tb1[s_hi]; tb1[s_hi] = s3; ti1[s_hi] = col0 + 1; }
                    else if (s3 > tb2[s_hi]) tb2[s_hi] = s3;
                    acc[mt][nt][0] = 0.f; acc[mt][nt][1] = 0.f;
                    acc[mt][nt][2] = 0.f; acc[mt][nt][3] = 0.f;
                }
            }
        }
    }

    #pragma unroll
    for (int s = 0; s < 8; ++s) {
        #pragma unroll
        for (int d = 1; d <= 2; d <<= 1) {
            float ob1 = __shfl_xor_sync(0xFFFFFFFFu, tb1[s], d);
            float ob2 = __shfl_xor_sync(0xFFFFFFFFu, tb2[s], d);
            int   oi1 = __shfl_xor_sync(0xFFFFFFFFu, ti1[s], d);
            merge2(tb1[s], ti1[s], tb2[s], ob1, oi1, ob2);
        }
    }

    __syncthreads();
    float* rv1 = (float*)smB;
    int*   ri1 = (int*)(smB + 2048);
    float* rv2 = (float*)(smB + 4096);
    int*   sidx = (int*)(smB + 6144);
    if ((lane & 3) == 0) {
        #pragma unroll
        for (int s = 0; s < 8; ++s) {
            int rowl = warp_m * 64 + (s >> 1) * 16 + ((s & 1) << 3) + (lane >> 2);
            rv1[rowl * 4 + warp_n] = tb1[s];
            ri1[rowl * 4 + warp_n] = ti1[s];
            rv2[rowl * 4 + warp_n] = tb2[s];
        }
    }
    __syncthreads();
    if (tid < BM) {
        float b1 = rv1[tid * 4]; int i1 = ri1[tid * 4]; float b2 = rv2[tid * 4];
        #pragma unroll
        for (int w = 1; w < 4; ++w)
            merge2(b1, i1, b2, rv1[tid * 4 + w], ri1[tid * 4 + w], rv2[tid * 4 + w]);
        g_indices[rowBase + tid] = i1;
        sidx[tid] = i1;
        if (b1 - b2 < MARGIN) {
            int p = atomicAdd(&g_flag_count, 1);
            if (p < CAP) g_flag_rows[p] = rowBase + tid;
        }
    }
    __syncthreads();

    for (int rr = wid * 16; rr < wid * 16 + 16; ++rr) {
        const int idx = sidx[rr];
        const int grow = rowBase + rr;
        const float* qrow = cbf + (size_t)idx * DDIM;
        const float* xrow = tokf + (size_t)grow * DDIM;
        float* orow = outp + (size_t)grow * DDIM;
        float s = 0.f;
        #pragma unroll
        for (int j = 0; j < 6; ++j) {
            const int ch = (j * 32 + lane) * 4;
            float4 q = *(const float4*)(qrow + ch);
            float4 x = *(const float4*)(xrow + ch);
            *(float4*)(orow + ch) = q;
            float dx = q.x - x.x, dy = q.y - x.y, dz = q.z - x.z, dw = q.w - x.w;
            s += dx * dx + dy * dy + dz * dz + dw * dw;
        }
        #pragma unroll
        for (int off = 16; off > 0; off >>= 1)
            s += __shfl_down_sync(0xFFFFFFFFu, s, off);
        if (lane == 0) {
            g_row_partial[grow] = s;
            if (write_indices) outp[(size_t)NTOK * DDIM + grow] = (float)idx;
        }
    }
}

// ---------------------------------------------------------------------------
// Exact fp32 rescue as batched tiled GEMM (unchanged)
// ---------------------------------------------------------------------------
__global__ __launch_bounds__(256) void rescue1_kernel(
    const float* __restrict__ token, const float* __restrict__ cbp)
{
    int cnt = g_flag_count; if (cnt > CAP) cnt = CAP;
    const int rg = blockIdx.x;
    if (rg * RG >= cnt) return;
    const int nb = blockIdx.y;

    extern __shared__ float rsm[];
    float* xs = rsm;
    float* ct = rsm + RG * XS_STRIDE;
    __shared__ float rv[256];
    __shared__ int   ri[256];

    const int tid = threadIdx.x;
    const int tr = tid & 15;
    const int tc = tid >> 4;

    {
        int slot = rg * RG + tr;
        int grow = (slot < cnt) ? g_flag_rows[slot] : 0;
        const float* src = token + (size_t)grow * DDIM;
        #pragma unroll
        for (int j = 0; j < 12; ++j) {
            int q = tc + j * 16;
            float4 v = *(const float4*)(src + q * 4);
            float* dst = xs + tr * XS_STRIDE + q * 4;
            dst[0] = v.x; dst[1] = v.y; dst[2] = v.z; dst[3] = v.w;
        }
    }

    float acc[8];
    #pragma unroll
    for (int j = 0; j < 8; ++j) acc[j] = 0.f;

    for (int kt = 0; kt < NKIT; ++kt) {
        __syncthreads();
        #pragma unroll
        for (int j = 0; j < 4; ++j) {
            int idx = tid + j * 256;
            int code = idx >> 3, q = idx & 7;
            float4 v = *(const float4*)(cbp + (size_t)(nb * 128 + code) * DDIM
                                        + kt * 32 + q * 4);
            ct[(q * 4 + 0) * CT_STRIDE + code] = v.x;
            ct[(q * 4 + 1) * CT_STRIDE + code] = v.y;
            ct[(q * 4 + 2) * CT_STRIDE + code] = v.z;
            ct[(q * 4 + 3) * CT_STRIDE + code] = v.w;
        }
        __syncthreads();
        #pragma unroll 4
        for (int kk = 0; kk < 32; ++kk) {
            float xv = xs[tr * XS_STRIDE + kt * 32 + kk];
            const float4 ca = *(const float4*)(ct + kk * CT_STRIDE + tc * 8);
            const float4 cb4 = *(const float4*)(ct + kk * CT_STRIDE + tc * 8 + 4);
            acc[0] += xv * ca.x; acc[1] += xv * ca.y;
            acc[2] += xv * ca.z; acc[3] += xv * ca.w;
            acc[4] += xv * cb4.x; acc[5] += xv * cb4.y;
            acc[6] += xv * cb4.z; acc[7] += xv * cb4.w;
        }
    }

    float bv = -3.4e38f; int bi = 0;
    #pragma unroll
    for (int j = 0; j < 8; ++j) {
        int code = nb * 128 + tc * 8 + j;
        float sc = acc[j] - g_half_esq[code];
        if (sc > bv) { bv = sc; bi = code; }
    }
    rv[tc * 16 + tr] = bv; ri[tc * 16 + tr] = bi;
    __syncthreads();
    if (tid < 16) {
        float b = rv[tid]; int i = ri[tid];
        #pragma unroll
        for (int c = 1; c < 16; ++c) {
            float v = rv[c * 16 + tid]; int ix = ri[c * 16 + tid];
            if (v > b || (v == b && ix < i)) { b = v; i = ix; }
        }
        int slot = rg * RG + tid;
        if (slot < cnt) { g_seg_val[slot][nb] = b; g_seg_idx[slot][nb] = i; }
    }
}

// ---------------------------------------------------------------------------
// Fixup: each block handles FIXG slots; rewrites output only on winner change.
// ---------------------------------------------------------------------------
__global__ __launch_bounds__(192) void fixup_kernel(
    const float* __restrict__ token, const float* __restrict__ cbf,
    float* __restrict__ out, int write_indices)
{
    int cnt = g_flag_count; if (cnt > CAP) cnt = CAP;
    const int base = blockIdx.x * FIXG;
    if (base >= cnt) return;
    __shared__ int s_bi, s_row, s_go;
    __shared__ float ws[6];
    const int t = threadIdx.x;

    for (int slot = base; slot < base + FIXG && slot < cnt; ++slot) {
        if (t == 0) {
            float bv = g_seg_val[slot][0]; int bi = g_seg_idx[slot][0];
            #pragma unroll
            for (int s2 = 1; s2 < RNB; ++s2) {
                float v = g_seg_val[slot][s2]; int ix = g_seg_idx[slot][s2];
                if (v > bv || (v == bv && ix < bi)) { bv = v; bi = ix; }
            }
            int row = g_flag_rows[slot];
            s_row = row; s_bi = bi;
            s_go = (g_indices[row] != bi);
            if (s_go) g_indices[row] = bi;
        }
        __syncthreads();
        if (s_go) {
            const int row = s_row, idx = s_bi;
            float4 q = *(const float4*)(cbf + (size_t)idx * DDIM + t * 4);
            float4 x = *(const float4*)(token + (size_t)row * DDIM + t * 4);
            *(float4*)(out + (size_t)row * DDIM + t * 4) = q;
            float dx = q.x - x.x, dy = q.y - x.y, dz = q.z - x.z, dw = q.w - x.w;
            float s = dx * dx + dy * dy + dz * dz + dw * dw;
            #pragma unroll
            for (int off = 16; off > 0; off >>= 1)
                s += __shfl_down_sync(0xFFFFFFFFu, s, off);
            if ((t & 31) == 0) ws[t >> 5] = s;
            __syncthreads();
            if (t == 0) {
                float tt = 0.f;
                #pragma unroll
                for (int w = 0; w < 6; w++) tt += ws[w];
                g_row_partial[row] = tt;
                if (write_indices) out[(size_t)NTOK * DDIM + row] = (float)idx;
            }
        }
        __syncthreads();
    }
}

// ---------------------------------------------------------------------------
__global__ void loss_kernel(float* __restrict__ out, long long out_size) {
    __shared__ float sm[1024];
    const float4* rp = (const float4*)g_row_partial;
    float s = 0.f;
    for (int i = threadIdx.x; i < NTOK / 4; i += 1024) {
        float4 v = rp[i];
        s += v.x + v.y + v.z + v.w;
    }
    sm[threadIdx.x] = s;
    __syncthreads();
    for (int off = 512; off > 0; off >>= 1) {
        if (threadIdx.x < off) sm[threadIdx.x] += sm[threadIdx.x + off];
        __syncthreads();
    }
    if (threadIdx.x == 0) {
        long long pos = (long long)NTOK * DDIM + NTOK;
        if (out_size > pos) out[pos] = sm[0] / (float)((long long)NTOK * DDIM);
    }
}

__global__ void fill_zero_kernel(float* __restrict__ p, long long n) {
    long long i = (long long)blockIdx.x * blockDim.x + threadIdx.x;
    if (i < n) p[i] = 0.f;
}

// ---------------------------------------------------------------------------
extern "C" void kernel_launch(void* const* d_in, const int* in_sizes, int n_in,
                              void* d_out, int out_size) {
    const float* token = (const float*)d_in[0];
    const float* cb    = (const float*)d_in[1];
    if (n_in >= 2 && in_sizes[0] == KCB * DDIM && in_sizes[1] == NTOK * DDIM) {
        const float* t = token; token = cb; cb = t;
    }
    float* out = (float*)d_out;

    __half* cb_h;
    cudaGetSymbolAddress((void**)&cb_h, g_cb_h);

    cudaFuncSetAttribute(vq_main_kernel,
                         cudaFuncAttributeMaxDynamicSharedMemorySize, SMEM_TOTAL);
    cudaFuncSetAttribute(rescue1_kernel,
                         cudaFuncAttributeMaxDynamicSharedMemorySize, RSMEM);

    long long osz = (long long)out_size;
    int write_indices = (osz >= (long long)NTOK * DDIM + NTOK) ? 1 : 0;

    esq_kernel<<<KCB, 256>>>(cb);
    vq_main_kernel<<<NTOK / BM, NT, SMEM_TOTAL>>>(token, cb_h, cb, out,
                                                  write_indices);
    rescue1_kernel<<<dim3(CAP / RG, RNB), 256, RSMEM>>>(token, cb);
    fixup_kernel<<<CAP / FIXG, 192>>>(token, cb, out, write_indices);
    loss_kernel<<<1, 1024>>>(out, osz);

    long long expected = (long long)NTOK * DDIM + NTOK + 1;
    if (osz > expected) {
        long long tail = osz - expected;
        int blocks = (int)((tail + 255) / 256);
        fill_zero_kernel<<<blocks, 256>>>(out + expected, tail);
    }
}

// round 10
// speedup vs baseline: 1.0126x; 1.0126x over previous
#include <cuda_runtime.h>
#include <cuda_fp16.h>
#include <cstdint>

#define DDIM 768
#define KCB  2048
#define NTOK 16384
#define BM   128
#define BN   128
#define BK   32
#define NKIT (DDIM / BK)        // 24 k-iters per N-block
#define NNB  (KCB / BN)         // 16 N-blocks
#define TOTIT (NKIT * NNB)      // 384
#define MARGIN 0.20f
#define CAP 4096
#define NT 256                  // threads in vq_main (8 warps, 2x4 grid)

#define A_BYTES (NKIT * 8192)   // 196608
#define B_BYTES (4 * 8192)      // 4-stage B ring
#define SMEM_TOTAL (A_BYTES + B_BYTES)   // 229376

// rescue tiling
#define RG  16
#define RNB 16
#define NGRP (CAP / RG)         // 256
#define XS_STRIDE 769
#define CT_STRIDE 132
#define RSMEM ((RG * XS_STRIDE + 32 * CT_STRIDE) * 4)   // 66112

// ---------------- device scratch ----------------
__device__ __half g_cb_h[KCB * DDIM];
__device__ float g_half_esq[KCB];
__device__ int   g_indices[NTOK];
__device__ float g_row_partial[NTOK];
__device__ int   g_flag_count;
__device__ int   g_flag_rows[CAP];
__device__ unsigned long long g_slot_best[CAP];
__device__ int   g_group_done[NGRP];
__device__ int   g_all_done;

// ---------------- helpers ----------------
__device__ __forceinline__ uint32_t smem_u32(const void* p) {
    uint32_t a;
    asm("{ .reg .u64 t; cvta.to.shared.u64 t, %1; cvt.u32.u64 %0, t; }"
        : "=r"(a) : "l"(p));
    return a;
}
#define CP_ASYNC16(dst, src) \
    asm volatile("cp.async.cg.shared.global [%0], [%1], 16;" :: "r"(dst), "l"(src))
#define CP_COMMIT() asm volatile("cp.async.commit_group;" ::: "memory")
#define CP_WAIT0()  asm volatile("cp.async.wait_group 0;" ::: "memory")
#define CP_WAIT2()  asm volatile("cp.async.wait_group 2;" ::: "memory")

__device__ __forceinline__ int swz16(int r, int c) {
    return (r >> 1) * 8 + ((((r & 1) << 2) | c) ^ ((r >> 1) & 7));
}
__device__ __forceinline__ void ldsm4(uint32_t* r, uint32_t addr) {
    asm volatile("ldmatrix.sync.aligned.m8n8.x4.shared.b16 {%0,%1,%2,%3}, [%4];"
                 : "=r"(r[0]), "=r"(r[1]), "=r"(r[2]), "=r"(r[3]) : "r"(addr));
}
__device__ __forceinline__ void mma16816(float* d, const uint32_t* a,
                                         uint32_t b0, uint32_t b1) {
    asm volatile(
        "mma.sync.aligned.m16n8k16.row.col.f32.f16.f16.f32 "
        "{%0,%1,%2,%3},{%4,%5,%6,%7},{%8,%9},{%0,%1,%2,%3};"
        : "+f"(d[0]), "+f"(d[1]), "+f"(d[2]), "+f"(d[3])
        : "r"(a[0]), "r"(a[1]), "r"(a[2]), "r"(a[3]), "r"(b0), "r"(b1));
}
__device__ __forceinline__ void merge2(float& b1, int& i1, float& b2,
                                       float ob1, int oi1, float ob2) {
    if (ob1 > b1 || (ob1 == b1 && oi1 < i1)) {
        b2 = fmaxf(b1, ob2); b1 = ob1; i1 = oi1;
    } else {
        b2 = fmaxf(b2, ob1);
    }
}
// pack (score, idx) so u64-max == (higher score, then LOWER idx)
__device__ __forceinline__ unsigned long long pack_si(float v, int idx) {
    uint32_t b = __float_as_uint(v);
    b = (b & 0x80000000u) ? ~b : (b | 0x80000000u);
    return ((unsigned long long)b << 32) | (unsigned)(0xFFFFFFFFu - (unsigned)idx);
}

__device__ __forceinline__ void load_frags(
    uint32_t (&af)[4][4], uint32_t (&bf)[2][4],
    uint32_t Ab, uint32_t Bb, int c0,
    int warp_m, int warp_n, int a_r, int a_c, int b_r, int b_c)
{
    #pragma unroll
    for (int mt = 0; mt < 4; ++mt)
        ldsm4(af[mt], Ab + swz16(warp_m * 64 + mt * 16 + a_r, c0 + a_c) * 16);
    #pragma unroll
    for (int np = 0; np < 2; ++np)
        ldsm4(bf[np], Bb + swz16(warp_n * 32 + np * 16 + b_r, c0 + b_c) * 16);
}

// ---------------------------------------------------------------------------
// esq: warp-per-row (8 rows/block), codebook fp16 conversion + counter resets
// ---------------------------------------------------------------------------
__global__ __launch_bounds__(256) void esq_kernel(const float* __restrict__ cbp) {
    const int tid = threadIdx.x;
    if (blockIdx.x == 0) {
        if (tid < NGRP) g_group_done[tid] = 0;
        if (tid == 0) { g_flag_count = 0; g_all_done = 0; }
    }
    const int warp = tid >> 5, lane = tid & 31;
    const int k = blockIdx.x * 8 + warp;
    const float4* row = (const float4*)(cbp + (size_t)k * DDIM);
    uint2* dst = (uint2*)(g_cb_h + (size_t)k * DDIM);
    float s = 0.f;
    #pragma unroll
    for (int j = 0; j < 6; ++j) {
        const int q = lane + j * 32;
        float4 v = row[q];
        s += v.x * v.x + v.y * v.y + v.z * v.z + v.w * v.w;
        __half2 h0 = __floats2half2_rn(v.x, v.y);
        __half2 h1 = __floats2half2_rn(v.z, v.w);
        uint2 o{*(uint32_t*)&h0, *(uint32_t*)&h1};
        dst[q] = o;
    }
    #pragma unroll
    for (int off = 16; off > 0; off >>= 1) s += __shfl_down_sync(0xFFFFFFFFu, s, off);
    if (lane == 0) g_half_esq[k] = 0.5f * s;
}

// ---------------------------------------------------------------------------
// Main fp16 mma.sync GEMM + argmax + FUSED gather/loss epilogue (as R8).
// ---------------------------------------------------------------------------
__global__ __launch_bounds__(NT, 1) void vq_main_kernel(
    const float* __restrict__ tokf, const __half* __restrict__ cbh,
    const float* __restrict__ cbf, float* __restrict__ outp, int write_indices)
{
    extern __shared__ char sm[];
    char* smA = sm;
    char* smB = sm + A_BYTES;

    const int tid = threadIdx.x;
    const int lane = tid & 31;
    const int wid = tid >> 5;
    const int warp_m = wid & 1;
    const int warp_n = wid >> 1;
    const int rowBase = blockIdx.x * BM;

    const uint32_t smA32 = smem_u32(smA);
    const uint32_t smB32 = smem_u32(smB);

    const int ld_r0 = tid >> 2, ld_c0 = tid & 3;
    const int ld_r1 = ld_r0 + 64;

    CP_ASYNC16(smB32 + swz16(ld_r0, ld_c0) * 16,
               cbh + (size_t)ld_r0 * DDIM + ld_c0 * 8);
    CP_ASYNC16(smB32 + swz16(ld_r1, ld_c0) * 16,
               cbh + (size_t)ld_r1 * DDIM + ld_c0 * 8);
    CP_COMMIT();
    CP_ASYNC16(smB32 + 8192 + swz16(ld_r0, ld_c0) * 16,
               cbh + (size_t)ld_r0 * DDIM + BK + ld_c0 * 8);
    CP_ASYNC16(smB32 + 8192 + swz16(ld_r1, ld_c0) * 16,
               cbh + (size_t)ld_r1 * DDIM + BK + ld_c0 * 8);
    CP_COMMIT();

    #pragma unroll 4
    for (int j = 0; j < 48; ++j) {
        int idx = tid + j * NT;
        int stage = idx >> 9;
        int within = idx & 511;
        int r = within >> 2, c2 = within & 3;
        const float* src = tokf + (size_t)(rowBase + r) * DDIM + stage * BK + c2 * 8;
        float4 a = *(const float4*)(src);
        float4 b = *(const float4*)(src + 4);
        __half2 h0 = __floats2half2_rn(a.x, a.y);
        __half2 h1 = __floats2half2_rn(a.z, a.w);
        __half2 h2 = __floats2half2_rn(b.x, b.y);
        __half2 h3 = __floats2half2_rn(b.z, b.w);
        uint4 o{*(uint32_t*)&h0, *(uint32_t*)&h1, *(uint32_t*)&h2, *(uint32_t*)&h3};
        *(uint4*)(smA + stage * 8192 + swz16(r, c2) * 16) = o;
    }

    float acc[4][4][4];
    #pragma unroll
    for (int mt = 0; mt < 4; ++mt)
        #pragma unroll
        for (int nt = 0; nt < 4; ++nt)
            #pragma unroll
            for (int e = 0; e < 4; ++e) acc[mt][nt][e] = 0.f;

    float tb1[8], tb2[8]; int ti1[8];
    #pragma unroll
    for (int s = 0; s < 8; ++s) { tb1[s] = -3.4e38f; tb2[s] = -3.4e38f; ti1[s] = 0x7FFFFFFF; }

    const int a_r = (lane & 15);
    const int a_c = (lane >> 4);
    const int b_r = ((lane >> 4) << 3) + (lane & 7);
    const int b_c = ((lane >> 3) & 1);

    uint32_t af[2][4][4];
    uint32_t bf[2][2][4];

    for (int ss = 0; ss < TOTIT / 2; ++ss) {
        __syncthreads();

        const int st0 = 2 * ss + 2;
        if (st0 < TOTIT) {
            #pragma unroll
            for (int j = 0; j < 2; ++j) {
                int st = st0 + j;
                int nb = st / NKIT, it = st % NKIT;
                const __half* base = cbh + (size_t)(nb * BN) * DDIM + it * BK + ld_c0 * 8;
                uint32_t dst = smB32 + (st & 3) * 8192;
                CP_ASYNC16(dst + swz16(ld_r0, ld_c0) * 16, base + (size_t)ld_r0 * DDIM);
                CP_ASYNC16(dst + swz16(ld_r1, ld_c0) * 16, base + (size_t)ld_r1 * DDIM);
                CP_COMMIT();
            }
            CP_WAIT2();
        } else {
            CP_WAIT0();
        }

        const int g0 = 2 * ss;
        const uint32_t Ab0 = smA32 + (g0 % NKIT) * 8192;
        const uint32_t Ab1 = smA32 + ((g0 + 1) % NKIT) * 8192;
        const uint32_t Bb0 = smB32 + (g0 & 3) * 8192;
        const uint32_t Bb1 = smB32 + ((g0 + 1) & 3) * 8192;

        load_frags(af[0], bf[0], Ab0, Bb0, 0, warp_m, warp_n, a_r, a_c, b_r, b_c);
        #pragma unroll
        for (int p = 0; p < 4; ++p) {
            const int cur = p & 1, nxt = cur ^ 1;
            if (p < 3) {
                const int pn = p + 1;
                load_frags(af[nxt], bf[nxt],
                           (pn >> 1) ? Ab1 : Ab0, (pn >> 1) ? Bb1 : Bb0,
                           (pn & 1) * 2, warp_m, warp_n, a_r, a_c, b_r, b_c);
            }
            #pragma unroll
            for (int mt = 0; mt < 4; ++mt)
                #pragma unroll
                for (int nt = 0; nt < 4; ++nt)
                    mma16816(acc[mt][nt], af[cur][mt],
                             bf[cur][nt >> 1][(nt & 1) * 2],
                             bf[cur][nt >> 1][(nt & 1) * 2 + 1]);
        }

        if (((g0 + 1) % NKIT) == NKIT - 1) {
            const int nbase = ((g0 + 1) / NKIT) * BN + warp_n * 32;
            #pragma unroll
            for (int mt = 0; mt < 4; ++mt) {
                #pragma unroll
                for (int nt = 0; nt < 4; ++nt) {
                    const int col0 = nbase + nt * 8 + (lane & 3) * 2;
                    const float he0 = __ldg(&g_half_esq[col0]);
                    const float he1 = __ldg(&g_half_esq[col0 + 1]);
                    float s0 = acc[mt][nt][0] - he0;
                    float s1 = acc[mt][nt][1] - he1;
                    float s2 = acc[mt][nt][2] - he0;
                    float s3 = acc[mt][nt][3] - he1;
                    const int s_lo = mt * 2, s_hi = mt * 2 + 1;
                    if (s0 > tb1[s_lo]) { tb2[s_lo] = tb1[s_lo]; tb1[s_lo] = s0; ti1[s_lo] = col0; }
                    else if (s0 > tb2[s_lo]) tb2[s_lo] = s0;
                    if (s1 > tb1[s_lo]) { tb2[s_lo] = tb1[s_lo]; tb1[s_lo] = s1; ti1[s_lo] = col0 + 1; }
                    else if (s1 > tb2[s_lo]) tb2[s_lo] = s1;
                    if (s2 > tb1[s_hi]) { tb2[s_hi] = tb1[s_hi]; tb1[s_hi] = s2; ti1[s_hi] = col0; }
                    else if (s2 > tb2[s_hi]) tb2[s_hi] = s2;
                    if (s3 > tb1[s_hi]) { tb2[s_hi] = tb1[s_hi]; tb1[s_hi] = s3; ti1[s_hi] = col0 + 1; }
                    else if (s3 > tb2[s_hi]) tb2[s_hi] = s3;
                    acc[mt][nt][0] = 0.f; acc[mt][nt][1] = 0.f;
                    acc[mt][nt][2] = 0.f; acc[mt][nt][3] = 0.f;
                }
            }
        }
    }

    #pragma unroll
    for (int s = 0; s < 8; ++s) {
        #pragma unroll
        for (int d = 1; d <= 2; d <<= 1) {
            float ob1 = __shfl_xor_sync(0xFFFFFFFFu, tb1[s], d);
            float ob2 = __shfl_xor_sync(0xFFFFFFFFu, tb2[s], d);
            int   oi1 = __shfl_xor_sync(0xFFFFFFFFu, ti1[s], d);
            merge2(tb1[s], ti1[s], tb2[s], ob1, oi1, ob2);
        }
    }

    __syncthreads();
    float* rv1 = (float*)smB;
    int*   ri1 = (int*)(smB + 2048);
    float* rv2 = (float*)(smB + 4096);
    int*   sidx = (int*)(smB + 6144);
    if ((lane & 3) == 0) {
        #pragma unroll
        for (int s = 0; s < 8; ++s) {
            int rowl = warp_m * 64 + (s >> 1) * 16 + ((s & 1) << 3) + (lane >> 2);
            rv1[rowl * 4 + warp_n] = tb1[s];
            ri1[rowl * 4 + warp_n] = ti1[s];
            rv2[rowl * 4 + warp_n] = tb2[s];
        }
    }
    __syncthreads();
    if (tid < BM) {
        float b1 = rv1[tid * 4]; int i1 = ri1[tid * 4]; float b2 = rv2[tid * 4];
        #pragma unroll
        for (int w = 1; w < 4; ++w)
            merge2(b1, i1, b2, rv1[tid * 4 + w], ri1[tid * 4 + w], rv2[tid * 4 + w]);
        g_indices[rowBase + tid] = i1;
        sidx[tid] = i1;
        if (b1 - b2 < MARGIN) {
            int p = atomicAdd(&g_flag_count, 1);
            if (p < CAP) { g_flag_rows[p] = rowBase + tid; g_slot_best[p] = 0ull; }
        }
    }
    __syncthreads();

    for (int rr = wid * 16; rr < wid * 16 + 16; ++rr) {
        const int idx = sidx[rr];
        const int grow = rowBase + rr;
        const float* qrow = cbf + (size_t)idx * DDIM;
        const float* xrow = tokf + (size_t)grow * DDIM;
        float* orow = outp + (size_t)grow * DDIM;
        float s = 0.f;
        #pragma unroll
        for (int j = 0; j < 6; ++j) {
            const int ch = (j * 32 + lane) * 4;
            float4 q = *(const float4*)(qrow + ch);
            float4 x = *(const float4*)(xrow + ch);
            *(float4*)(orow + ch) = q;
            float dx = q.x - x.x, dy = q.y - x.y, dz = q.z - x.z, dw = q.w - x.w;
            s += dx * dx + dy * dy + dz * dz + dw * dw;
        }
        #pragma unroll
        for (int off = 16; off > 0; off >>= 1)
            s += __shfl_down_sync(0xFFFFFFFFu, s, off);
        if (lane == 0) {
            g_row_partial[grow] = s;
            if (write_indices) outp[(size_t)NTOK * DDIM + grow] = (float)idx;
        }
    }
}

// ---------------------------------------------------------------------------
// Rescue + fixup + loss in ONE kernel (last-block merge pattern).
// ---------------------------------------------------------------------------
__device__ __forceinline__ void do_loss(float* __restrict__ out,
                                        long long out_size, int tid) {
    __shared__ float lsm[256];
    const float4* rp = (const float4*)g_row_partial;
    float s = 0.f;
    #pragma unroll
    for (int j = 0; j < 16; ++j) {
        float4 v = rp[tid + j * 256];
        s += v.x + v.y + v.z + v.w;
    }
    lsm[tid] = s;
    __syncthreads();
    for (int off = 128; off > 0; off >>= 1) {
        if (tid < off) lsm[tid] += lsm[tid + off];
        __syncthreads();
    }
    if (tid == 0) {
        long long pos = (long long)NTOK * DDIM + NTOK;
        if (out_size > pos) out[pos] = lsm[0] / (float)((long long)NTOK * DDIM);
    }
}

__global__ __launch_bounds__(256) void rescue_kernel(
    const float* __restrict__ token, const float* __restrict__ cbp,
    float* __restrict__ out, long long out_size, int write_indices)
{
    const int tid = threadIdx.x;
    int cnt = g_flag_count; if (cnt > CAP) cnt = CAP;
    const int rg = blockIdx.x;
    const int nb = blockIdx.y;

    if (cnt == 0) {
        if (rg == 0 && nb == 0) do_loss(out, out_size, tid);
        return;
    }
    if (rg * RG >= cnt) return;
    const int n_groups = (cnt + RG - 1) / RG;

    extern __shared__ float rsm[];
    float* xs = rsm;
    float* ct = rsm + RG * XS_STRIDE;
    __shared__ float rv[256];
    __shared__ int   ri[256];
    __shared__ int   s_last, s_loss;

    const int tr = tid & 15;
    const int tc = tid >> 4;

    {
        int slot = rg * RG + tr;
        int grow = (slot < cnt) ? g_flag_rows[slot] : 0;
        const float* src = token + (size_t)grow * DDIM;
        #pragma unroll
        for (int j = 0; j < 12; ++j) {
            int q = tc + j * 16;
            float4 v = *(const float4*)(src + q * 4);
            float* dst = xs + tr * XS_STRIDE + q * 4;
            dst[0] = v.x; dst[1] = v.y; dst[2] = v.z; dst[3] = v.w;
        }
    }

    float acc[8];
    #pragma unroll
    for (int j = 0; j < 8; ++j) acc[j] = 0.f;

    for (int kt = 0; kt < NKIT; ++kt) {
        __syncthreads();
        #pragma unroll
        for (int j = 0; j < 4; ++j) {
            int idx = tid + j * 256;
            int code = idx >> 3, q = idx & 7;
            float4 v = *(const float4*)(cbp + (size_t)(nb * 128 + code) * DDIM
                                        + kt * 32 + q * 4);
            ct[(q * 4 + 0) * CT_STRIDE + code] = v.x;
            ct[(q * 4 + 1) * CT_STRIDE + code] = v.y;
            ct[(q * 4 + 2) * CT_STRIDE + code] = v.z;
            ct[(q * 4 + 3) * CT_STRIDE + code] = v.w;
        }
        __syncthreads();
        #pragma unroll 4
        for (int kk = 0; kk < 32; ++kk) {
            float xv = xs[tr * XS_STRIDE + kt * 32 + kk];
            const float4 ca = *(const float4*)(ct + kk * CT_STRIDE + tc * 8);
            const float4 cb4 = *(const float4*)(ct + kk * CT_STRIDE + tc * 8 + 4);
            acc[0] += xv * ca.x; acc[1] += xv * ca.y;
            acc[2] += xv * ca.z; acc[3] += xv * ca.w;
            acc[4] += xv * cb4.x; acc[5] += xv * cb4.y;
            acc[6] += xv * cb4.z; acc[7] += xv * cb4.w;
        }
    }

    float bv = -3.4e38f; int bi = 0;
    #pragma unroll
    for (int j = 0; j < 8; ++j) {
        int code = nb * 128 + tc * 8 + j;
        float sc = acc[j] - g_half_esq[code];
        if (sc > bv) { bv = sc; bi = code; }
    }
    rv[tc * 16 + tr] = bv; ri[tc * 16 + tr] = bi;
    __syncthreads();
    if (tid < 16) {
        float b = rv[tid]; int i = ri[tid];
        #pragma unroll
        for (int c = 1; c < 16; ++c) {
            float v = rv[c * 16 + tid]; int ix = ri[c * 16 + tid];
            if (v > b || (v == b && ix < i)) { b = v; i = ix; }
        }
        int slot = rg * RG + tid;
        if (slot < cnt) atomicMax(&g_slot_best[slot], pack_si(b, i));
    }
    __threadfence();
    __syncthreads();
    if (tid == 0) s_last = (atomicAdd(&g_group_done[rg], 1) == RNB - 1);
    __syncthreads();
    if (!s_last) return;

    // last nb-block of this group: fixup its slots
    __threadfence();
    __shared__ int f_row, f_idx, f_go;
    __shared__ float ws[8];
    const int slot_end = min(rg * RG + RG, cnt);
    for (int slot = rg * RG; slot < slot_end; ++slot) {
        if (tid == 0) {
            unsigned long long p = g_slot_best[slot];
            int bi2 = (int)(0xFFFFFFFFu - (unsigned)(p & 0xFFFFFFFFu));
            int row = g_flag_rows[slot];
            f_row = row; f_idx = bi2;
            f_go = (g_indices[row] != bi2);
            if (f_go) g_indices[row] = bi2;
        }
        __syncthreads();
        if (f_go) {
            const int row = f_row, idx = f_idx;
            float s = 0.f;
            if (tid < 192) {
                float4 q = *(const float4*)(cbp + (size_t)idx * DDIM + tid * 4);
                float4 x = *(const float4*)(token + (size_t)row * DDIM + tid * 4);
                *(float4*)(out + (size_t)row * DDIM + tid * 4) = q;
                float dx = q.x - x.x, dy = q.y - x.y, dz = q.z - x.z, dw = q.w - x.w;
                s = dx * dx + dy * dy + dz * dz + dw * dw;
            }
            #pragma unroll
            for (int off = 16; off > 0; off >>= 1)
                s += __shfl_down_sync(0xFFFFFFFFu, s, off);
            if ((tid & 31) == 0) ws[tid >> 5] = s;
            __syncthreads();
            if (tid == 0) {
                float tt = 0.f;
                #pragma unroll
                for (int w = 0; w < 8; w++) tt += ws[w];
                g_row_partial[row] = tt;
                if (write_indices) out[(size_t)NTOK * DDIM + row] = (float)idx;
            }
        }
        __syncthreads();
    }

    // last group overall: loss
    __threadfence();
    if (tid == 0) s_loss = (atomicAdd(&g_all_done, 1) == n_groups - 1);
    __syncthreads();
    if (s_loss) {
        __threadfence();
        do_loss(out, out_size, tid);
    }
}

__global__ void fill_zero_kernel(float* __restrict__ p, long long n) {
    long long i = (long long)blockIdx.x * blockDim.x + threadIdx.x;
    if (i < n) p[i] = 0.f;
}

// ---------------------------------------------------------------------------
extern "C" void kernel_launch(void* const* d_in, const int* in_sizes, int n_in,
                              void* d_out, int out_size) {
    const float* token = (const float*)d_in[0];
    const float* cb    = (const float*)d_in[1];
    if (n_in >= 2 && in_sizes[0] == KCB * DDIM && in_sizes[1] == NTOK * DDIM) {
        const float* t = token; token = cb; cb = t;
    }
    float* out = (float*)d_out;

    __half* cb_h;
    cudaGetSymbolAddress((void**)&cb_h, g_cb_h);

    cudaFuncSetAttribute(vq_main_kernel,
                         cudaFuncAttributeMaxDynamicSharedMemorySize, SMEM_TOTAL);
    cudaFuncSetAttribute(rescue_kernel,
                         cudaFuncAttributeMaxDynamicSharedMemorySize, RSMEM);

    long long osz = (long long)out_size;
    int write_indices = (osz >= (long long)NTOK * DDIM + NTOK) ? 1 : 0;

    esq_kernel<<<KCB / 8, 256>>>(cb);
    vq_main_kernel<<<NTOK / BM, NT, SMEM_TOTAL>>>(token, cb_h, cb, out,
                                                  write_indices);
    rescue_kernel<<<dim3(NGRP, RNB), 256, RSMEM>>>(token, cb, out, osz,
                                                   write_indices);

    long long expected = (long long)NTOK * DDIM + NTOK + 1;
    if (osz > expected) {
        long long tail = osz - expected;
        int blocks = (int)((tail + 255) / 256);
        fill_zero_kernel<<<blocks, 256>>>(out + expected, tail);
    }
}

// round 11
// speedup vs baseline: 1.0212x; 1.0085x over previous
#include <cuda_runtime.h>
#include <cuda_fp16.h>
#include <cstdint>

#define DDIM 768
#define KCB  2048
#define NTOK 16384
#define BM   128
#define BN   128
#define BK   32
#define NKIT (DDIM / BK)        // 24 k-iters per N-block
#define NNB  (KCB / BN)         // 16 N-blocks
#define TOTIT (NKIT * NNB)      // 384
#define MARGIN 0.20f
#define CAP 1024
#define NT 256                  // threads in vq_main (8 warps, 2x4 grid)

#define A_BYTES (NKIT * 8192)   // 196608
#define B_BYTES (4 * 8192)      // 4-stage B ring
#define SMEM_TOTAL (A_BYTES + B_BYTES)   // 229376

// rescue tiling (full-rescue fallback; expected nearly empty)
#define RG  16
#define RNB 16
#define NGRP (CAP / RG)         // 64
#define XS_STRIDE 769
#define CT_STRIDE 132
#define RSMEM ((RG * XS_STRIDE + 32 * CT_STRIDE) * 4)   // 66112

// ---------------- device scratch ----------------
__device__ __half g_cb_h[KCB * DDIM];
__device__ float g_half_esq[KCB];
__device__ int   g_indices[NTOK];
__device__ float g_row_partial[NTOK];
__device__ int   g_flag_count;
__device__ int   g_flag_rows[CAP];
__device__ unsigned long long g_slot_best[CAP];
__device__ int   g_group_done[NGRP];
__device__ int   g_all_done;

// ---------------- helpers ----------------
__device__ __forceinline__ uint32_t smem_u32(const void* p) {
    uint32_t a;
    asm("{ .reg .u64 t; cvta.to.shared.u64 t, %1; cvt.u32.u64 %0, t; }"
        : "=r"(a) : "l"(p));
    return a;
}
#define CP_ASYNC16(dst, src) \
    asm volatile("cp.async.cg.shared.global [%0], [%1], 16;" :: "r"(dst), "l"(src))
#define CP_COMMIT() asm volatile("cp.async.commit_group;" ::: "memory")
#define CP_WAIT0()  asm volatile("cp.async.wait_group 0;" ::: "memory")
#define CP_WAIT2()  asm volatile("cp.async.wait_group 2;" ::: "memory")

__device__ __forceinline__ int swz16(int r, int c) {
    return (r >> 1) * 8 + ((((r & 1) << 2) | c) ^ ((r >> 1) & 7));
}
__device__ __forceinline__ void ldsm4(uint32_t* r, uint32_t addr) {
    asm volatile("ldmatrix.sync.aligned.m8n8.x4.shared.b16 {%0,%1,%2,%3}, [%4];"
                 : "=r"(r[0]), "=r"(r[1]), "=r"(r[2]), "=r"(r[3]) : "r"(addr));
}
__device__ __forceinline__ void mma16816(float* d, const uint32_t* a,
                                         uint32_t b0, uint32_t b1) {
    asm volatile(
        "mma.sync.aligned.m16n8k16.row.col.f32.f16.f16.f32 "
        "{%0,%1,%2,%3},{%4,%5,%6,%7},{%8,%9},{%0,%1,%2,%3};"
        : "+f"(d[0]), "+f"(d[1]), "+f"(d[2]), "+f"(d[3])
        : "r"(a[0]), "r"(a[1]), "r"(a[2]), "r"(a[3]), "r"(b0), "r"(b1));
}
__device__ __forceinline__ void merge2(float& b1, int& i1, float& b2,
                                       float ob1, int oi1, float ob2) {
    if (ob1 > b1 || (ob1 == b1 && oi1 < i1)) {
        b2 = fmaxf(b1, ob2); b1 = ob1; i1 = oi1;
    } else {
        b2 = fmaxf(b2, ob1);
    }
}
// pack (score, idx) so u64-max == (higher score, then LOWER idx)
__device__ __forceinline__ unsigned long long pack_si(float v, int idx) {
    uint32_t b = __float_as_uint(v);
    b = (b & 0x80000000u) ? ~b : (b | 0x80000000u);
    return ((unsigned long long)b << 32) | (unsigned)(0xFFFFFFFFu - (unsigned)idx);
}

__device__ __forceinline__ void load_frags(
    uint32_t (&af)[4][4], uint32_t (&bf)[2][4],
    uint32_t Ab, uint32_t Bb, int c0,
    int warp_m, int warp_n, int a_r, int a_c, int b_r, int b_c)
{
    #pragma unroll
    for (int mt = 0; mt < 4; ++mt)
        ldsm4(af[mt], Ab + swz16(warp_m * 64 + mt * 16 + a_r, c0 + a_c) * 16);
    #pragma unroll
    for (int np = 0; np < 2; ++np)
        ldsm4(bf[np], Bb + swz16(warp_n * 32 + np * 16 + b_r, c0 + b_c) * 16);
}

// ---------------------------------------------------------------------------
// esq: warp-per-row (8 rows/block), codebook fp16 conversion + counter resets
// ---------------------------------------------------------------------------
__global__ __launch_bounds__(256) void esq_kernel(const float* __restrict__ cbp) {
    const int tid = threadIdx.x;
    if (blockIdx.x == 0) {
        if (tid < NGRP) g_group_done[tid] = 0;
        if (tid == 0) { g_flag_count = 0; g_all_done = 0; }
    }
    const int warp = tid >> 5, lane = tid & 31;
    const int k = blockIdx.x * 8 + warp;
    const float4* row = (const float4*)(cbp + (size_t)k * DDIM);
    uint2* dst = (uint2*)(g_cb_h + (size_t)k * DDIM);
    float s = 0.f;
    #pragma unroll
    for (int j = 0; j < 6; ++j) {
        const int q = lane + j * 32;
        float4 v = row[q];
        s += v.x * v.x + v.y * v.y + v.z * v.z + v.w * v.w;
        __half2 h0 = __floats2half2_rn(v.x, v.y);
        __half2 h1 = __floats2half2_rn(v.z, v.w);
        uint2 o{*(uint32_t*)&h0, *(uint32_t*)&h1};
        dst[q] = o;
    }
    #pragma unroll
    for (int off = 16; off > 0; off >>= 1) s += __shfl_down_sync(0xFFFFFFFFu, s, off);
    if (lane == 0) g_half_esq[k] = 0.5f * s;
}

// ---------------------------------------------------------------------------
// Main fp16 mma.sync GEMM + argmax + in-kernel exact candidate re-scoring
// + fused gather/loss epilogue.
// ---------------------------------------------------------------------------
__global__ __launch_bounds__(NT, 1) void vq_main_kernel(
    const float* __restrict__ tokf, const __half* __restrict__ cbh,
    const float* __restrict__ cbf, float* __restrict__ outp, int write_indices)
{
    extern __shared__ char sm[];
    char* smA = sm;
    char* smB = sm + A_BYTES;

    const int tid = threadIdx.x;
    const int lane = tid & 31;
    const int wid = tid >> 5;
    const int warp_m = wid & 1;
    const int warp_n = wid >> 1;
    const int rowBase = blockIdx.x * BM;

    const uint32_t smA32 = smem_u32(smA);
    const uint32_t smB32 = smem_u32(smB);

    const int ld_r0 = tid >> 2, ld_c0 = tid & 3;
    const int ld_r1 = ld_r0 + 64;

    CP_ASYNC16(smB32 + swz16(ld_r0, ld_c0) * 16,
               cbh + (size_t)ld_r0 * DDIM + ld_c0 * 8);
    CP_ASYNC16(smB32 + swz16(ld_r1, ld_c0) * 16,
               cbh + (size_t)ld_r1 * DDIM + ld_c0 * 8);
    CP_COMMIT();
    CP_ASYNC16(smB32 + 8192 + swz16(ld_r0, ld_c0) * 16,
               cbh + (size_t)ld_r0 * DDIM + BK + ld_c0 * 8);
    CP_ASYNC16(smB32 + 8192 + swz16(ld_r1, ld_c0) * 16,
               cbh + (size_t)ld_r1 * DDIM + BK + ld_c0 * 8);
    CP_COMMIT();

    #pragma unroll 4
    for (int j = 0; j < 48; ++j) {
        int idx = tid + j * NT;
        int stage = idx >> 9;
        int within = idx & 511;
        int r = within >> 2, c2 = within & 3;
        const float* src = tokf + (size_t)(rowBase + r) * DDIM + stage * BK + c2 * 8;
        float4 a = *(const float4*)(src);
        float4 b = *(const float4*)(src + 4);
        __half2 h0 = __floats2half2_rn(a.x, a.y);
        __half2 h1 = __floats2half2_rn(a.z, a.w);
        __half2 h2 = __floats2half2_rn(b.x, b.y);
        __half2 h3 = __floats2half2_rn(b.z, b.w);
        uint4 o{*(uint32_t*)&h0, *(uint32_t*)&h1, *(uint32_t*)&h2, *(uint32_t*)&h3};
        *(uint4*)(smA + stage * 8192 + swz16(r, c2) * 16) = o;
    }

    float acc[4][4][4];
    #pragma unroll
    for (int mt = 0; mt < 4; ++mt)
        #pragma unroll
        for (int nt = 0; nt < 4; ++nt)
            #pragma unroll
            for (int e = 0; e < 4; ++e) acc[mt][nt][e] = 0.f;

    float tb1[8], tb2[8]; int ti1[8];
    #pragma unroll
    for (int s = 0; s < 8; ++s) { tb1[s] = -3.4e38f; tb2[s] = -3.4e38f; ti1[s] = 0x7FFFFFFF; }

    const int a_r = (lane & 15);
    const int a_c = (lane >> 4);
    const int b_r = ((lane >> 4) << 3) + (lane & 7);
    const int b_c = ((lane >> 3) & 1);

    uint32_t af[2][4][4];
    uint32_t bf[2][2][4];

    for (int ss = 0; ss < TOTIT / 2; ++ss) {
        __syncthreads();

        const int st0 = 2 * ss + 2;
        if (st0 < TOTIT) {
            #pragma unroll
            for (int j = 0; j < 2; ++j) {
                int st = st0 + j;
                int nb = st / NKIT, it = st % NKIT;
                const __half* base = cbh + (size_t)(nb * BN) * DDIM + it * BK + ld_c0 * 8;
                uint32_t dst = smB32 + (st & 3) * 8192;
                CP_ASYNC16(dst + swz16(ld_r0, ld_c0) * 16, base + (size_t)ld_r0 * DDIM);
                CP_ASYNC16(dst + swz16(ld_r1, ld_c0) * 16, base + (size_t)ld_r1 * DDIM);
                CP_COMMIT();
            }
            CP_WAIT2();
        } else {
            CP_WAIT0();
        }

        const int g0 = 2 * ss;
        const uint32_t Ab0 = smA32 + (g0 % NKIT) * 8192;
        const uint32_t Ab1 = smA32 + ((g0 + 1) % NKIT) * 8192;
        const uint32_t Bb0 = smB32 + (g0 & 3) * 8192;
        const uint32_t Bb1 = smB32 + ((g0 + 1) & 3) * 8192;

        load_frags(af[0], bf[0], Ab0, Bb0, 0, warp_m, warp_n, a_r, a_c, b_r, b_c);
        #pragma unroll
        for (int p = 0; p < 4; ++p) {
            const int cur = p & 1, nxt = cur ^ 1;
            if (p < 3) {
                const int pn = p + 1;
                load_frags(af[nxt], bf[nxt],
                           (pn >> 1) ? Ab1 : Ab0, (pn >> 1) ? Bb1 : Bb0,
                           (pn & 1) * 2, warp_m, warp_n, a_r, a_c, b_r, b_c);
            }
            #pragma unroll
            for (int mt = 0; mt < 4; ++mt)
                #pragma unroll
                for (int nt = 0; nt < 4; ++nt)
                    mma16816(acc[mt][nt], af[cur][mt],
                             bf[cur][nt >> 1][(nt & 1) * 2],
                             bf[cur][nt >> 1][(nt & 1) * 2 + 1]);
        }

        if (((g0 + 1) % NKIT) == NKIT - 1) {
            const int nbase = ((g0 + 1) / NKIT) * BN + warp_n * 32;
            #pragma unroll
            for (int mt = 0; mt < 4; ++mt) {
                #pragma unroll
                for (int nt = 0; nt < 4; ++nt) {
                    const int col0 = nbase + nt * 8 + (lane & 3) * 2;
                    const float he0 = __ldg(&g_half_esq[col0]);
                    const float he1 = __ldg(&g_half_esq[col0 + 1]);
                    float s0 = acc[mt][nt][0] - he0;
                    float s1 = acc[mt][nt][1] - he1;
                    float s2 = acc[mt][nt][2] - he0;
                    float s3 = acc[mt][nt][3] - he1;
                    const int s_lo = mt * 2, s_hi = mt * 2 + 1;
                    if (s0 > tb1[s_lo]) { tb2[s_lo] = tb1[s_lo]; tb1[s_lo] = s0; ti1[s_lo] = col0; }
                    else if (s0 > tb2[s_lo]) tb2[s_lo] = s0;
                    if (s1 > tb1[s_lo]) { tb2[s_lo] = tb1[s_lo]; tb1[s_lo] = s1; ti1[s_lo] = col0 + 1; }
                    else if (s1 > tb2[s_lo]) tb2[s_lo] = s1;
                    if (s2 > tb1[s_hi]) { tb2[s_hi] = tb1[s_hi]; tb1[s_hi] = s2; ti1[s_hi] = col0; }
                    else if (s2 > tb2[s_hi]) tb2[s_hi] = s2;
                    if (s3 > tb1[s_hi]) { tb2[s_hi] = tb1[s_hi]; tb1[s_hi] = s3; ti1[s_hi] = col0 + 1; }
                    else if (s3 > tb2[s_hi]) tb2[s_hi] = s3;
                    acc[mt][nt][0] = 0.f; acc[mt][nt][1] = 0.f;
                    acc[mt][nt][2] = 0.f; acc[mt][nt][3] = 0.f;
                }
            }
        }
    }

    #pragma unroll
    for (int s = 0; s < 8; ++s) {
        #pragma unroll
        for (int d = 1; d <= 2; d <<= 1) {
            float ob1 = __shfl_xor_sync(0xFFFFFFFFu, tb1[s], d);
            float ob2 = __shfl_xor_sync(0xFFFFFFFFu, tb2[s], d);
            int   oi1 = __shfl_xor_sync(0xFFFFFFFFu, ti1[s], d);
            merge2(tb1[s], ti1[s], tb2[s], ob1, oi1, ob2);
        }
    }

    __syncthreads();
    // smem layout in B ring (all mainloop readers done):
    float* rv1 = (float*)smB;                 // [128][4]
    int*   ri1 = (int*)(smB + 2048);
    float* rv2 = (float*)(smB + 4096);
    int*   sidx = (int*)(smB + 6144);         // [128]
    int*   pcnt = (int*)(smB + 6656);
    int*   pend_row = (int*)(smB + 7168);     // [128]
    int*   pend_nc  = (int*)(smB + 7680);     // [128]
    int*   pend_cand = (int*)(smB + 8192);    // [128][4]
    if (tid == 0) *pcnt = 0;
    if ((lane & 3) == 0) {
        #pragma unroll
        for (int s = 0; s < 8; ++s) {
            int rowl = warp_m * 64 + (s >> 1) * 16 + ((s & 1) << 3) + (lane >> 2);
            rv1[rowl * 4 + warp_n] = tb1[s];
            ri1[rowl * 4 + warp_n] = ti1[s];
            rv2[rowl * 4 + warp_n] = tb2[s];
        }
    }
    __syncthreads();
    if (tid < BM) {
        float g1[4], g2[4]; int gi[4];
        #pragma unroll
        for (int w = 0; w < 4; ++w) {
            g1[w] = rv1[tid * 4 + w]; gi[w] = ri1[tid * 4 + w]; g2[w] = rv2[tid * 4 + w];
        }
        // fp16 provisional winner (lowest-index ties)
        float b1 = g1[0]; int i1 = gi[0];
        #pragma unroll
        for (int w = 1; w < 4; ++w)
            if (g1[w] > b1 || (g1[w] == b1 && gi[w] < i1)) { b1 = g1[w]; i1 = gi[w]; }
        const float thr = b1 - MARGIN;
        bool full = false;
        int nc = 0; int cd[4];
        #pragma unroll
        for (int w = 0; w < 4; ++w) {
            if (g2[w] >= thr) full = true;
            if (g1[w] >= thr) cd[nc++] = gi[w];
        }
        if (full) {
            int p = atomicAdd(&g_flag_count, 1);
            if (p < CAP) { g_flag_rows[p] = rowBase + tid; g_slot_best[p] = 0ull; }
        } else if (nc > 1) {
            int p = atomicAdd(pcnt, 1);
            pend_row[p] = tid; pend_nc[p] = nc;
            #pragma unroll
            for (int c = 0; c < 4; ++c)
                if (c < nc) pend_cand[p * 4 + c] = cd[c];
        }
        g_indices[rowBase + tid] = i1;
        sidx[tid] = i1;
    }
    __syncthreads();

    // exact fp32 re-scoring of multi-candidate rows (warp per pending row)
    {
        const int P = *pcnt;
        for (int pi = wid; pi < P; pi += 8) {
            const int rl = pend_row[pi];
            const int nc = pend_nc[pi];
            const float* xrow = tokf + (size_t)(rowBase + rl) * DDIM;
            float4 xr[6];
            #pragma unroll
            for (int j = 0; j < 6; ++j)
                xr[j] = *(const float4*)(xrow + (j * 32 + lane) * 4);
            float best = -3.4e38f; int bidx = 0x7FFFFFFF;
            for (int c = 0; c < nc; ++c) {
                const int ci = pend_cand[pi * 4 + c];
                const float* erow = cbf + (size_t)ci * DDIM;
                float s = 0.f;
                #pragma unroll
                for (int j = 0; j < 6; ++j) {
                    float4 e = *(const float4*)(erow + (j * 32 + lane) * 4);
                    s += xr[j].x * e.x + xr[j].y * e.y + xr[j].z * e.z + xr[j].w * e.w;
                }
                #pragma unroll
                for (int off = 16; off > 0; off >>= 1)
                    s += __shfl_down_sync(0xFFFFFFFFu, s, off);
                if (lane == 0) {
                    float sc = s - g_half_esq[ci];
                    if (sc > best || (sc == best && ci < bidx)) { best = sc; bidx = ci; }
                }
            }
            if (lane == 0) {
                sidx[rl] = bidx;
                g_indices[rowBase + rl] = bidx;
            }
        }
    }
    __syncthreads();

    // fused gather + loss-partial epilogue
    for (int rr = wid * 16; rr < wid * 16 + 16; ++rr) {
        const int idx = sidx[rr];
        const int grow = rowBase + rr;
        const float* qrow = cbf + (size_t)idx * DDIM;
        const float* xrow = tokf + (size_t)grow * DDIM;
        float* orow = outp + (size_t)grow * DDIM;
        float s = 0.f;
        #pragma unroll
        for (int j = 0; j < 6; ++j) {
            const int ch = (j * 32 + lane) * 4;
            float4 q = *(const float4*)(qrow + ch);
            float4 x = *(const float4*)(xrow + ch);
            *(float4*)(orow + ch) = q;
            float dx = q.x - x.x, dy = q.y - x.y, dz = q.z - x.z, dw = q.w - x.w;
            s += dx * dx + dy * dy + dz * dz + dw * dw;
        }
        #pragma unroll
        for (int off = 16; off > 0; off >>= 1)
            s += __shfl_down_sync(0xFFFFFFFFu, s, off);
        if (lane == 0) {
            g_row_partial[grow] = s;
            if (write_indices) outp[(size_t)NTOK * DDIM + grow] = (float)idx;
        }
    }
}

// ---------------------------------------------------------------------------
// Full rescue + fixup + loss (safety net; expected ~0-8 rows)
// ---------------------------------------------------------------------------
__device__ __forceinline__ void do_loss(float* __restrict__ out,
                                        long long out_size, int tid) {
    __shared__ float lsm[256];
    const float4* rp = (const float4*)g_row_partial;
    float s = 0.f;
    #pragma unroll
    for (int j = 0; j < 16; ++j) {
        float4 v = rp[tid + j * 256];
        s += v.x + v.y + v.z + v.w;
    }
    lsm[tid] = s;
    __syncthreads();
    for (int off = 128; off > 0; off >>= 1) {
        if (tid < off) lsm[tid] += lsm[tid + off];
        __syncthreads();
    }
    if (tid == 0) {
        long long pos = (long long)NTOK * DDIM + NTOK;
        if (out_size > pos) out[pos] = lsm[0] / (float)((long long)NTOK * DDIM);
    }
}

__global__ __launch_bounds__(256) void rescue_kernel(
    const float* __restrict__ token, const float* __restrict__ cbp,
    float* __restrict__ out, long long out_size, int write_indices)
{
    const int tid = threadIdx.x;
    int cnt = g_flag_count; if (cnt > CAP) cnt = CAP;
    const int rg = blockIdx.x;
    const int nb = blockIdx.y;

    if (cnt == 0) {
        if (rg == 0 && nb == 0) do_loss(out, out_size, tid);
        return;
    }
    if (rg * RG >= cnt) return;
    const int n_groups = (cnt + RG - 1) / RG;

    extern __shared__ float rsm[];
    float* xs = rsm;
    float* ct = rsm + RG * XS_STRIDE;
    __shared__ float rv[256];
    __shared__ int   ri[256];
    __shared__ int   s_last, s_loss;

    const int tr = tid & 15;
    const int tc = tid >> 4;

    {
        int slot = rg * RG + tr;
        int grow = (slot < cnt) ? g_flag_rows[slot] : 0;
        const float* src = token + (size_t)grow * DDIM;
        #pragma unroll
        for (int j = 0; j < 12; ++j) {
            int q = tc + j * 16;
            float4 v = *(const float4*)(src + q * 4);
            float* dst = xs + tr * XS_STRIDE + q * 4;
            dst[0] = v.x; dst[1] = v.y; dst[2] = v.z; dst[3] = v.w;
        }
    }

    float acc[8];
    #pragma unroll
    for (int j = 0; j < 8; ++j) acc[j] = 0.f;

    for (int kt = 0; kt < NKIT; ++kt) {
        __syncthreads();
        #pragma unroll
        for (int j = 0; j < 4; ++j) {
            int idx = tid + j * 256;
            int code = idx >> 3, q = idx & 7;
            float4 v = *(const float4*)(cbp + (size_t)(nb * 128 + code) * DDIM
                                        + kt * 32 + q * 4);
            ct[(q * 4 + 0) * CT_STRIDE + code] = v.x;
            ct[(q * 4 + 1) * CT_STRIDE + code] = v.y;
            ct[(q * 4 + 2) * CT_STRIDE + code] = v.z;
            ct[(q * 4 + 3) * CT_STRIDE + code] = v.w;
        }
        __syncthreads();
        #pragma unroll 4
        for (int kk = 0; kk < 32; ++kk) {
            float xv = xs[tr * XS_STRIDE + kt * 32 + kk];
            const float4 ca = *(const float4*)(ct + kk * CT_STRIDE + tc * 8);
            const float4 cb4 = *(const float4*)(ct + kk * CT_STRIDE + tc * 8 + 4);
            acc[0] += xv * ca.x; acc[1] += xv * ca.y;
            acc[2] += xv * ca.z; acc[3] += xv * ca.w;
            acc[4] += xv * cb4.x; acc[5] += xv * cb4.y;
            acc[6] += xv * cb4.z; acc[7] += xv * cb4.w;
        }
    }

    float bv = -3.4e38f; int bi = 0;
    #pragma unroll
    for (int j = 0; j < 8; ++j) {
        int code = nb * 128 + tc * 8 + j;
        float sc = acc[j] - g_half_esq[code];
        if (sc > bv) { bv = sc; bi = code; }
    }
    rv[tc * 16 + tr] = bv; ri[tc * 16 + tr] = bi;
    __syncthreads();
    if (tid < 16) {
        float b = rv[tid]; int i = ri[tid];
        #pragma unroll
        for (int c = 1; c < 16; ++c) {
            float v = rv[c * 16 + tid]; int ix = ri[c * 16 + tid];
            if (v > b || (v == b && ix < i)) { b = v; i = ix; }
        }
        int slot = rg * RG + tid;
        if (slot < cnt) atomicMax(&g_slot_best[slot], pack_si(b, i));
    }
    __threadfence();
    __syncthreads();
    if (tid == 0) s_last = (atomicAdd(&g_group_done[rg], 1) == RNB - 1);
    __syncthreads();
    if (!s_last) return;

    __threadfence();
    __shared__ int f_row, f_idx, f_go;
    __shared__ float ws[8];
    const int slot_end = min(rg * RG + RG, cnt);
    for (int slot = rg * RG; slot < slot_end; ++slot) {
        if (tid == 0) {
            unsigned long long p = g_slot_best[slot];
            int bi2 = (int)(0xFFFFFFFFu - (unsigned)(p & 0xFFFFFFFFu));
            int row = g_flag_rows[slot];
            f_row = row; f_idx = bi2;
            f_go = (g_indices[row] != bi2);
            if (f_go) g_indices[row] = bi2;
        }
        __syncthreads();
        if (f_go) {
            const int row = f_row, idx = f_idx;
            float s = 0.f;
            if (tid < 192) {
                float4 q = *(const float4*)(cbp + (size_t)idx * DDIM + tid * 4);
                float4 x = *(const float4*)(token + (size_t)row * DDIM + tid * 4);
                *(float4*)(out + (size_t)row * DDIM + tid * 4) = q;
                float dx = q.x - x.x, dy = q.y - x.y, dz = q.z - x.z, dw = q.w - x.w;
                s = dx * dx + dy * dy + dz * dz + dw * dw;
            }
            #pragma unroll
            for (int off = 16; off > 0; off >>= 1)
                s += __shfl_down_sync(0xFFFFFFFFu, s, off);
            if ((tid & 31) == 0) ws[tid >> 5] = s;
            __syncthreads();
            if (tid == 0) {
                float tt = 0.f;
                #pragma unroll
                for (int w = 0; w < 8; w++) tt += ws[w];
                g_row_partial[row] = tt;
                if (write_indices) out[(size_t)NTOK * DDIM + row] = (float)idx;
            }
        }
        __syncthreads();
    }

    __threadfence();
    if (tid == 0) s_loss = (atomicAdd(&g_all_done, 1) == n_groups - 1);
    __syncthreads();
    if (s_loss) {
        __threadfence();
        do_loss(out, out_size, tid);
    }
}

__global__ void fill_zero_kernel(float* __restrict__ p, long long n) {
    long long i = (long long)blockIdx.x * blockDim.x + threadIdx.x;
    if (i < n) p[i] = 0.f;
}

// ---------------------------------------------------------------------------
extern "C" void kernel_launch(void* const* d_in, const int* in_sizes, int n_in,
                              void* d_out, int out_size) {
    const float* token = (const float*)d_in[0];
    const float* cb    = (const float*)d_in[1];
    if (n_in >= 2 && in_sizes[0] == KCB * DDIM && in_sizes[1] == NTOK * DDIM) {
        const float* t = token; token = cb; cb = t;
    }
    float* out = (float*)d_out;

    __half* cb_h;
    cudaGetSymbolAddress((void**)&cb_h, g_cb_h);

    cudaFuncSetAttribute(vq_main_kernel,
                         cudaFuncAttributeMaxDynamicSharedMemorySize, SMEM_TOTAL);
    cudaFuncSetAttribute(rescue_kernel,
                         cudaFuncAttributeMaxDynamicSharedMemorySize, RSMEM);

    long long osz = (long long)out_size;
    int write_indices = (osz >= (long long)NTOK * DDIM + NTOK) ? 1 : 0;

    esq_kernel<<<KCB / 8, 256>>>(cb);
    vq_main_kernel<<<NTOK / BM, NT, SMEM_TOTAL>>>(token, cb_h, cb, out,
                                                  write_indices);
    rescue_kernel<<<dim3(NGRP, RNB), 256, RSMEM>>>(token, cb, out, osz,
                                                   write_indices);

    long long expected = (long long)NTOK * DDIM + NTOK + 1;
    if (osz > expected) {
        long long tail = osz - expected;
        int blocks = (int)((tail + 255) / 256);
        fill_zero_kernel<<<blocks, 256>>>(out + expected, tail);
    }
}

// round 12
// speedup vs baseline: 1.0826x; 1.0601x over previous
#include <cuda_runtime.h>
#include <cuda_fp16.h>
#include <cstdint>

#define DDIM 768
#define KCB  2048
#define NTOK 16384
#define BM   128
#define BN   128
#define BK   32
#define NKIT (DDIM / BK)        // 24 k-iters per N-block
#define NNB  (KCB / BN)         // 16 N-blocks
#define TOTIT (NKIT * NNB)      // 384
#define MARGIN 0.20f
#define CAP 1024
#define NT 256                  // threads in vq_main (8 warps, 2x4 grid)

#define A_BYTES (NKIT * 8192)   // 196608
#define B_BYTES (4 * 8192)      // 4-stage B ring
#define SMEM_TOTAL (A_BYTES + B_BYTES)   // 229376

// rescue tiling (full-rescue fallback; expected small)
#define RG  16
#define RNB 16
#define NGRP (CAP / RG)         // 64
#define XS_STRIDE 769
#define CT_STRIDE 132
#define RSMEM ((RG * XS_STRIDE + 32 * CT_STRIDE) * 4)   // 66112

// ---------------- device scratch ----------------
__device__ __half g_cb_h[KCB * DDIM];
__device__ float g_half_esq[KCB];
__device__ int   g_indices[NTOK];
__device__ float g_row_partial[NTOK];
__device__ int   g_flag_count;
__device__ int   g_flag_rows[CAP];
__device__ unsigned long long g_slot_best[CAP];
__device__ int   g_group_done[NGRP];
__device__ int   g_all_done;

// ---------------- helpers ----------------
__device__ __forceinline__ uint32_t smem_u32(const void* p) {
    uint32_t a;
    asm("{ .reg .u64 t; cvta.to.shared.u64 t, %1; cvt.u32.u64 %0, t; }"
        : "=r"(a) : "l"(p));
    return a;
}
#define CP_ASYNC16(dst, src) \
    asm volatile("cp.async.cg.shared.global [%0], [%1], 16;" :: "r"(dst), "l"(src))
#define CP_COMMIT() asm volatile("cp.async.commit_group;" ::: "memory")
#define CP_WAIT0()  asm volatile("cp.async.wait_group 0;" ::: "memory")
#define CP_WAIT2()  asm volatile("cp.async.wait_group 2;" ::: "memory")

__device__ __forceinline__ int swz16(int r, int c) {
    return (r >> 1) * 8 + ((((r & 1) << 2) | c) ^ ((r >> 1) & 7));
}
__device__ __forceinline__ void ldsm4(uint32_t* r, uint32_t addr) {
    asm volatile("ldmatrix.sync.aligned.m8n8.x4.shared.b16 {%0,%1,%2,%3}, [%4];"
                 : "=r"(r[0]), "=r"(r[1]), "=r"(r[2]), "=r"(r[3]) : "r"(addr));
}
__device__ __forceinline__ void mma16816(float* d, const uint32_t* a,
                                         uint32_t b0, uint32_t b1) {
    asm volatile(
        "mma.sync.aligned.m16n8k16.row.col.f32.f16.f16.f32 "
        "{%0,%1,%2,%3},{%4,%5,%6,%7},{%8,%9},{%0,%1,%2,%3};"
        : "+f"(d[0]), "+f"(d[1]), "+f"(d[2]), "+f"(d[3])
        : "r"(a[0]), "r"(a[1]), "r"(a[2]), "r"(a[3]), "r"(b0), "r"(b1));
}
__device__ __forceinline__ void merge2(float& b1, int& i1, float& b2,
                                       float ob1, int oi1, float ob2) {
    if (ob1 > b1 || (ob1 == b1 && oi1 < i1)) {
        b2 = fmaxf(b1, ob2); b1 = ob1; i1 = oi1;
    } else {
        b2 = fmaxf(b2, ob1);
    }
}
// pack (score, idx) so u64-max == (higher score, then LOWER idx)
__device__ __forceinline__ unsigned long long pack_si(float v, int idx) {
    uint32_t b = __float_as_uint(v);
    b = (b & 0x80000000u) ? ~b : (b | 0x80000000u);
    return ((unsigned long long)b << 32) | (unsigned)(0xFFFFFFFFu - (unsigned)idx);
}

__device__ __forceinline__ void load_frags(
    uint32_t (&af)[4][4], uint32_t (&bf)[2][4],
    uint32_t Ab, uint32_t Bb, int c0,
    int warp_m, int warp_n, int a_r, int a_c, int b_r, int b_c)
{
    #pragma unroll
    for (int mt = 0; mt < 4; ++mt)
        ldsm4(af[mt], Ab + swz16(warp_m * 64 + mt * 16 + a_r, c0 + a_c) * 16);
    #pragma unroll
    for (int np = 0; np < 2; ++np)
        ldsm4(bf[np], Bb + swz16(warp_n * 32 + np * 16 + b_r, c0 + b_c) * 16);
}

// convert one 16B chunk (8 fp32 -> 8 fp16) into swizzled smA
__device__ __forceinline__ void conv_chunk(char* smA, const float* tokf,
                                           int rowBase, int stage, int within)
{
    int r = within >> 2, c2 = within & 3;
    const float* src = tokf + (size_t)(rowBase + r) * DDIM + stage * BK + c2 * 8;
    float4 a = *(const float4*)(src);
    float4 b = *(const float4*)(src + 4);
    __half2 h0 = __floats2half2_rn(a.x, a.y);
    __half2 h1 = __floats2half2_rn(a.z, a.w);
    __half2 h2 = __floats2half2_rn(b.x, b.y);
    __half2 h3 = __floats2half2_rn(b.z, b.w);
    uint4 o{*(uint32_t*)&h0, *(uint32_t*)&h1, *(uint32_t*)&h2, *(uint32_t*)&h3};
    *(uint4*)(smA + stage * 8192 + swz16(r, c2) * 16) = o;
}

// ---------------------------------------------------------------------------
// esq: warp-per-row (8 rows/block), codebook fp16 conversion + counter resets
// ---------------------------------------------------------------------------
__global__ __launch_bounds__(256) void esq_kernel(const float* __restrict__ cbp) {
    const int tid = threadIdx.x;
    if (blockIdx.x == 0) {
        if (tid < NGRP) g_group_done[tid] = 0;
        if (tid == 0) { g_flag_count = 0; g_all_done = 0; }
    }
    const int warp = tid >> 5, lane = tid & 31;
    const int k = blockIdx.x * 8 + warp;
    const float4* row = (const float4*)(cbp + (size_t)k * DDIM);
    uint2* dst = (uint2*)(g_cb_h + (size_t)k * DDIM);
    float s = 0.f;
    #pragma unroll
    for (int j = 0; j < 6; ++j) {
        const int q = lane + j * 32;
        float4 v = row[q];
        s += v.x * v.x + v.y * v.y + v.z * v.z + v.w * v.w;
        __half2 h0 = __floats2half2_rn(v.x, v.y);
        __half2 h1 = __floats2half2_rn(v.z, v.w);
        uint2 o{*(uint32_t*)&h0, *(uint32_t*)&h1};
        dst[q] = o;
    }
    #pragma unroll
    for (int off = 16; off > 0; off >>= 1) s += __shfl_down_sync(0xFFFFFFFFu, s, off);
    if (lane == 0) g_half_esq[k] = 0.5f * s;
}

// ---------------------------------------------------------------------------
// Main fp16 mma.sync GEMM + argmax + candidate re-scoring + fused epilogue.
// A-conversion overlapped with the mainloop (stages 6..23 converted in-loop).
// ---------------------------------------------------------------------------
__global__ __launch_bounds__(NT, 1) void vq_main_kernel(
    const float* __restrict__ tokf, const __half* __restrict__ cbh,
    const float* __restrict__ cbf, float* __restrict__ outp, int write_indices)
{
    extern __shared__ char sm[];
    char* smA = sm;
    char* smB = sm + A_BYTES;

    const int tid = threadIdx.x;
    const int lane = tid & 31;
    const int wid = tid >> 5;
    const int warp_m = wid & 1;
    const int warp_n = wid >> 1;
    const int rowBase = blockIdx.x * BM;

    const uint32_t smA32 = smem_u32(smA);
    const uint32_t smB32 = smem_u32(smB);

    const int ld_r0 = tid >> 2, ld_c0 = tid & 3;
    const int ld_r1 = ld_r0 + 64;

    CP_ASYNC16(smB32 + swz16(ld_r0, ld_c0) * 16,
               cbh + (size_t)ld_r0 * DDIM + ld_c0 * 8);
    CP_ASYNC16(smB32 + swz16(ld_r1, ld_c0) * 16,
               cbh + (size_t)ld_r1 * DDIM + ld_c0 * 8);
    CP_COMMIT();
    CP_ASYNC16(smB32 + 8192 + swz16(ld_r0, ld_c0) * 16,
               cbh + (size_t)ld_r0 * DDIM + BK + ld_c0 * 8);
    CP_ASYNC16(smB32 + 8192 + swz16(ld_r1, ld_c0) * 16,
               cbh + (size_t)ld_r1 * DDIM + BK + ld_c0 * 8);
    CP_COMMIT();

    // Prologue: convert only stages 0..5 (rest overlapped in-loop)
    #pragma unroll 4
    for (int j = 0; j < 12; ++j) {
        int idx = tid + j * NT;            // 0..3071 chunks (stages 0-5)
        conv_chunk(smA, tokf, rowBase, idx >> 9, idx & 511);
    }

    float acc[4][4][4];
    #pragma unroll
    for (int mt = 0; mt < 4; ++mt)
        #pragma unroll
        for (int nt = 0; nt < 4; ++nt)
            #pragma unroll
            for (int e = 0; e < 4; ++e) acc[mt][nt][e] = 0.f;

    float tb1[8], tb2[8]; int ti1[8];
    #pragma unroll
    for (int s = 0; s < 8; ++s) { tb1[s] = -3.4e38f; tb2[s] = -3.4e38f; ti1[s] = 0x7FFFFFFF; }

    const int a_r = (lane & 15);
    const int a_c = (lane >> 4);
    const int b_r = ((lane >> 4) << 3) + (lane & 7);
    const int b_c = ((lane >> 3) & 1);

    uint32_t af[2][4][4];
    uint32_t bf[2][2][4];

    for (int ss = 0; ss < TOTIT / 2; ++ss) {
        __syncthreads();

        const int st0 = 2 * ss + 2;
        if (st0 < TOTIT) {
            #pragma unroll
            for (int j = 0; j < 2; ++j) {
                int st = st0 + j;
                int nb = st / NKIT, it = st % NKIT;
                const __half* base = cbh + (size_t)(nb * BN) * DDIM + it * BK + ld_c0 * 8;
                uint32_t dst = smB32 + (st & 3) * 8192;
                CP_ASYNC16(dst + swz16(ld_r0, ld_c0) * 16, base + (size_t)ld_r0 * DDIM);
                CP_ASYNC16(dst + swz16(ld_r1, ld_c0) * 16, base + (size_t)ld_r1 * DDIM);
                CP_COMMIT();
            }
            CP_WAIT2();
        } else {
            CP_WAIT0();
        }

        const int g0 = 2 * ss;
        const uint32_t Ab0 = smA32 + (g0 % NKIT) * 8192;
        const uint32_t Ab1 = smA32 + ((g0 + 1) % NKIT) * 8192;
        const uint32_t Bb0 = smB32 + (g0 & 3) * 8192;
        const uint32_t Bb1 = smB32 + ((g0 + 1) & 3) * 8192;

        load_frags(af[0], bf[0], Ab0, Bb0, 0, warp_m, warp_n, a_r, a_c, b_r, b_c);
        #pragma unroll
        for (int p = 0; p < 4; ++p) {
            const int cur = p & 1, nxt = cur ^ 1;
            if (p < 3) {
                const int pn = p + 1;
                load_frags(af[nxt], bf[nxt],
                           (pn >> 1) ? Ab1 : Ab0, (pn >> 1) ? Bb1 : Bb0,
                           (pn & 1) * 2, warp_m, warp_n, a_r, a_c, b_r, b_c);
            }
            #pragma unroll
            for (int mt = 0; mt < 4; ++mt)
                #pragma unroll
                for (int nt = 0; nt < 4; ++nt)
                    mma16816(acc[mt][nt], af[cur][mt],
                             bf[cur][nt >> 1][(nt & 1) * 2],
                             bf[cur][nt >> 1][(nt & 1) * 2 + 1]);
        }

        // overlapped A-conversion: stages 6..23, 4 per superstep (ss 0..4)
        if (ss < 5) {
            const int cstage = 6 + ss * 4;
            #pragma unroll
            for (int cj = 0; cj < 4; ++cj) {
                int stg = cstage + cj;
                if (stg < NKIT) {
                    conv_chunk(smA, tokf, rowBase, stg, tid);
                    conv_chunk(smA, tokf, rowBase, stg, tid + 256);
                }
            }
        }

        if (((g0 + 1) % NKIT) == NKIT - 1) {
            const int nbase = ((g0 + 1) / NKIT) * BN + warp_n * 32;
            #pragma unroll
            for (int mt = 0; mt < 4; ++mt) {
                #pragma unroll
                for (int nt = 0; nt < 4; ++nt) {
                    const int col0 = nbase + nt * 8 + (lane & 3) * 2;
                    const float he0 = __ldg(&g_half_esq[col0]);
                    const float he1 = __ldg(&g_half_esq[col0 + 1]);
                    float s0 = acc[mt][nt][0] - he0;
                    float s1 = acc[mt][nt][1] - he1;
                    float s2 = acc[mt][nt][2] - he0;
                    float s3 = acc[mt][nt][3] - he1;
                    const int s_lo = mt * 2, s_hi = mt * 2 + 1;
                    if (s0 > tb1[s_lo]) { tb2[s_lo] = tb1[s_lo]; tb1[s_lo] = s0; ti1[s_lo] = col0; }
                    else if (s0 > tb2[s_lo]) tb2[s_lo] = s0;
                    if (s1 > tb1[s_lo]) { tb2[s_lo] = tb1[s_lo]; tb1[s_lo] = s1; ti1[s_lo] = col0 + 1; }
                    else if (s1 > tb2[s_lo]) tb2[s_lo] = s1;
                    if (s2 > tb1[s_hi]) { tb2[s_hi] = tb1[s_hi]; tb1[s_hi] = s2; ti1[s_hi] = col0; }
                    else if (s2 > tb2[s_hi]) tb2[s_hi] = s2;
                    if (s3 > tb1[s_hi]) { tb2[s_hi] = tb1[s_hi]; tb1[s_hi] = s3; ti1[s_hi] = col0 + 1; }
                    else if (s3 > tb2[s_hi]) tb2[s_hi] = s3;
                    acc[mt][nt][0] = 0.f; acc[mt][nt][1] = 0.f;
                    acc[mt][nt][2] = 0.f; acc[mt][nt][3] = 0.f;
                }
            }
        }
    }

    #pragma unroll
    for (int s = 0; s < 8; ++s) {
        #pragma unroll
        for (int d = 1; d <= 2; d <<= 1) {
            float ob1 = __shfl_xor_sync(0xFFFFFFFFu, tb1[s], d);
            float ob2 = __shfl_xor_sync(0xFFFFFFFFu, tb2[s], d);
            int   oi1 = __shfl_xor_sync(0xFFFFFFFFu, ti1[s], d);
            merge2(tb1[s], ti1[s], tb2[s], ob1, oi1, ob2);
        }
    }

    __syncthreads();
    float* rv1 = (float*)smB;                 // [128][4]
    int*   ri1 = (int*)(smB + 2048);
    float* rv2 = (float*)(smB + 4096);
    int*   sidx = (int*)(smB + 6144);         // [128]
    int*   pcnt = (int*)(smB + 6656);
    int*   pend_row = (int*)(smB + 7168);     // [128]
    int*   pend_nc  = (int*)(smB + 7680);     // [128]
    int*   pend_cand = (int*)(smB + 8192);    // [128][4]
    if (tid == 0) *pcnt = 0;
    if ((lane & 3) == 0) {
        #pragma unroll
        for (int s = 0; s < 8; ++s) {
            int rowl = warp_m * 64 + (s >> 1) * 16 + ((s & 1) << 3) + (lane >> 2);
            rv1[rowl * 4 + warp_n] = tb1[s];
            ri1[rowl * 4 + warp_n] = ti1[s];
            rv2[rowl * 4 + warp_n] = tb2[s];
        }
    }
    __syncthreads();
    if (tid < BM) {
        float g1[4], g2[4]; int gi[4];
        #pragma unroll
        for (int w = 0; w < 4; ++w) {
            g1[w] = rv1[tid * 4 + w]; gi[w] = ri1[tid * 4 + w]; g2[w] = rv2[tid * 4 + w];
        }
        float b1 = g1[0]; int i1 = gi[0];
        #pragma unroll
        for (int w = 1; w < 4; ++w)
            if (g1[w] > b1 || (g1[w] == b1 && gi[w] < i1)) { b1 = g1[w]; i1 = gi[w]; }
        const float thr = b1 - MARGIN;
        bool full = false;
        int nc = 0; int cd[4];
        #pragma unroll
        for (int w = 0; w < 4; ++w) {
            if (g2[w] >= thr) full = true;
            if (g1[w] >= thr) cd[nc++] = gi[w];
        }
        if (full) {
            int p = atomicAdd(&g_flag_count, 1);
            if (p < CAP) { g_flag_rows[p] = rowBase + tid; g_slot_best[p] = 0ull; }
        } else if (nc > 1) {
            int p = atomicAdd(pcnt, 1);
            pend_row[p] = tid; pend_nc[p] = nc;
            #pragma unroll
            for (int c = 0; c < 4; ++c)
                if (c < nc) pend_cand[p * 4 + c] = cd[c];
        }
        g_indices[rowBase + tid] = i1;
        sidx[tid] = i1;
    }
    __syncthreads();

    // exact fp32 re-scoring of multi-candidate rows (warp per pending row)
    {
        const int P = *pcnt;
        for (int pi = wid; pi < P; pi += 8) {
            const int rl = pend_row[pi];
            const int nc = pend_nc[pi];
            const float* xrow = tokf + (size_t)(rowBase + rl) * DDIM;
            float4 xr[6];
            #pragma unroll
            for (int j = 0; j < 6; ++j)
                xr[j] = *(const float4*)(xrow + (j * 32 + lane) * 4);
            float best = -3.4e38f; int bidx = 0x7FFFFFFF;
            for (int c = 0; c < nc; ++c) {
                const int ci = pend_cand[pi * 4 + c];
                const float* erow = cbf + (size_t)ci * DDIM;
                float s = 0.f;
                #pragma unroll
                for (int j = 0; j < 6; ++j) {
                    float4 e = *(const float4*)(erow + (j * 32 + lane) * 4);
                    s += xr[j].x * e.x + xr[j].y * e.y + xr[j].z * e.z + xr[j].w * e.w;
                }
                #pragma unroll
                for (int off = 16; off > 0; off >>= 1)
                    s += __shfl_down_sync(0xFFFFFFFFu, s, off);
                if (lane == 0) {
                    float sc = s - g_half_esq[ci];
                    if (sc > best || (sc == best && ci < bidx)) { best = sc; bidx = ci; }
                }
            }
            if (lane == 0) {
                sidx[rl] = bidx;
                g_indices[rowBase + rl] = bidx;
            }
        }
    }
    __syncthreads();

    // fused gather + loss-partial epilogue: x read from resident fp16 A tile
    for (int rr = wid * 16; rr < wid * 16 + 16; ++rr) {
        const int idx = sidx[rr];
        const int grow = rowBase + rr;
        const float* qrow = cbf + (size_t)idx * DDIM;
        float* orow = outp + (size_t)grow * DDIM;
        float s = 0.f;
        #pragma unroll
        for (int jj = 0; jj < 3; ++jj) {
            const int ch = lane + jj * 32;          // chunk 0..95
            const int stage = ch >> 2, c2 = ch & 3;
            const int d0 = ch * 8;
            float4 q0 = *(const float4*)(qrow + d0);
            float4 q1 = *(const float4*)(qrow + d0 + 4);
            uint4 xv = *(const uint4*)(smA + stage * 8192 + swz16(rr, c2) * 16);
            float2 x0 = __half22float2(*(__half2*)&xv.x);
            float2 x1 = __half22float2(*(__half2*)&xv.y);
            float2 x2 = __half22float2(*(__half2*)&xv.z);
            float2 x3 = __half22float2(*(__half2*)&xv.w);
            *(float4*)(orow + d0) = q0;
            *(float4*)(orow + d0 + 4) = q1;
            float d;
            d = q0.x - x0.x; s += d * d;
            d = q0.y - x0.y; s += d * d;
            d = q0.z - x1.x; s += d * d;
            d = q0.w - x1.y; s += d * d;
            d = q1.x - x2.x; s += d * d;
            d = q1.y - x2.y; s += d * d;
            d = q1.z - x3.x; s += d * d;
            d = q1.w - x3.y; s += d * d;
        }
        #pragma unroll
        for (int off = 16; off > 0; off >>= 1)
            s += __shfl_down_sync(0xFFFFFFFFu, s, off);
        if (lane == 0) {
            g_row_partial[grow] = s;
            if (write_indices) outp[(size_t)NTOK * DDIM + grow] = (float)idx;
        }
    }
}

// ---------------------------------------------------------------------------
// Full rescue + fixup + loss (safety net)
// ---------------------------------------------------------------------------
__device__ __forceinline__ void do_loss(float* __restrict__ out,
                                        long long out_size, int tid) {
    __shared__ float lsm[256];
    const float4* rp = (const float4*)g_row_partial;
    float s = 0.f;
    #pragma unroll
    for (int j = 0; j < 16; ++j) {
        float4 v = rp[tid + j * 256];
        s += v.x + v.y + v.z + v.w;
    }
    lsm[tid] = s;
    __syncthreads();
    for (int off = 128; off > 0; off >>= 1) {
        if (tid < off) lsm[tid] += lsm[tid + off];
        __syncthreads();
    }
    if (tid == 0) {
        long long pos = (long long)NTOK * DDIM + NTOK;
        if (out_size > pos) out[pos] = lsm[0] / (float)((long long)NTOK * DDIM);
    }
}

__global__ __launch_bounds__(256) void rescue_kernel(
    const float* __restrict__ token, const float* __restrict__ cbp,
    float* __restrict__ out, long long out_size, int write_indices)
{
    const int tid = threadIdx.x;
    int cnt = g_flag_count; if (cnt > CAP) cnt = CAP;
    const int rg = blockIdx.x;
    const int nb = blockIdx.y;

    if (cnt == 0) {
        if (rg == 0 && nb == 0) do_loss(out, out_size, tid);
        return;
    }
    if (rg * RG >= cnt) return;
    const int n_groups = (cnt + RG - 1) / RG;

    extern __shared__ float rsm[];
    float* xs = rsm;
    float* ct = rsm + RG * XS_STRIDE;
    __shared__ float rv[256];
    __shared__ int   ri[256];
    __shared__ int   s_last, s_loss;

    const int tr = tid & 15;
    const int tc = tid >> 4;

    {
        int slot = rg * RG + tr;
        int grow = (slot < cnt) ? g_flag_rows[slot] : 0;
        const float* src = token + (size_t)grow * DDIM;
        #pragma unroll
        for (int j = 0; j < 12; ++j) {
            int q = tc + j * 16;
            float4 v = *(const float4*)(src + q * 4);
            float* dst = xs + tr * XS_STRIDE + q * 4;
            dst[0] = v.x; dst[1] = v.y; dst[2] = v.z; dst[3] = v.w;
        }
    }

    float acc[8];
    #pragma unroll
    for (int j = 0; j < 8; ++j) acc[j] = 0.f;

    for (int kt = 0; kt < NKIT; ++kt) {
        __syncthreads();
        #pragma unroll
        for (int j = 0; j < 4; ++j) {
            int idx = tid + j * 256;
            int code = idx >> 3, q = idx & 7;
            float4 v = *(const float4*)(cbp + (size_t)(nb * 128 + code) * DDIM
                                        + kt * 32 + q * 4);
            ct[(q * 4 + 0) * CT_STRIDE + code] = v.x;
            ct[(q * 4 + 1) * CT_STRIDE + code] = v.y;
            ct[(q * 4 + 2) * CT_STRIDE + code] = v.z;
            ct[(q * 4 + 3) * CT_STRIDE + code] = v.w;
        }
        __syncthreads();
        #pragma unroll 4
        for (int kk = 0; kk < 32; ++kk) {
            float xv = xs[tr * XS_STRIDE + kt * 32 + kk];
            const float4 ca = *(const float4*)(ct + kk * CT_STRIDE + tc * 8);
            const float4 cb4 = *(const float4*)(ct + kk * CT_STRIDE + tc * 8 + 4);
            acc[0] += xv * ca.x; acc[1] += xv * ca.y;
            acc[2] += xv * ca.z; acc[3] += xv * ca.w;
            acc[4] += xv * cb4.x; acc[5] += xv * cb4.y;
            acc[6] += xv * cb4.z; acc[7] += xv * cb4.w;
        }
    }

    float bv = -3.4e38f; int bi = 0;
    #pragma unroll
    for (int j = 0; j < 8; ++j) {
        int code = nb * 128 + tc * 8 + j;
        float sc = acc[j] - g_half_esq[code];
        if (sc > bv) { bv = sc; bi = code; }
    }
    rv[tc * 16 + tr] = bv; ri[tc * 16 + tr] = bi;
    __syncthreads();
    if (tid < 16) {
        float b = rv[tid]; int i = ri[tid];
        #pragma unroll
        for (int c = 1; c < 16; ++c) {
            float v = rv[c * 16 + tid]; int ix = ri[c * 16 + tid];
            if (v > b || (v == b && ix < i)) { b = v; i = ix; }
        }
        int slot = rg * RG + tid;
        if (slot < cnt) atomicMax(&g_slot_best[slot], pack_si(b, i));
    }
    __threadfence();
    __syncthreads();
    if (tid == 0) s_last = (atomicAdd(&g_group_done[rg], 1) == RNB - 1);
    __syncthreads();
    if (!s_last) return;

    __threadfence();
    __shared__ int f_row, f_idx, f_go;
    __shared__ float ws[8];
    const int slot_end = min(rg * RG + RG, cnt);
    for (int slot = rg * RG; slot < slot_end; ++slot) {
        if (tid == 0) {
            unsigned long long p = g_slot_best[slot];
            int bi2 = (int)(0xFFFFFFFFu - (unsigned)(p & 0xFFFFFFFFu));
            int row = g_flag_rows[slot];
            f_row = row; f_idx = bi2;
            f_go = (g_indices[row] != bi2);
            if (f_go) g_indices[row] = bi2;
        }
        __syncthreads();
        if (f_go) {
            const int row = f_row, idx = f_idx;
            float s = 0.f;
            if (tid < 192) {
                float4 q = *(const float4*)(cbp + (size_t)idx * DDIM + tid * 4);
                float4 x = *(const float4*)(token + (size_t)row * DDIM + tid * 4);
                *(float4*)(out + (size_t)row * DDIM + tid * 4) = q;
                float dx = q.x - x.x, dy = q.y - x.y, dz = q.z - x.z, dw = q.w - x.w;
                s = dx * dx + dy * dy + dz * dz + dw * dw;
            }
            #pragma unroll
            for (int off = 16; off > 0; off >>= 1)
                s += __shfl_down_sync(0xFFFFFFFFu, s, off);
            if ((tid & 31) == 0) ws[tid >> 5] = s;
            __syncthreads();
            if (tid == 0) {
                float tt = 0.f;
                #pragma unroll
                for (int w = 0; w < 8; w++) tt += ws[w];
                g_row_partial[row] = tt;
                if (write_indices) out[(size_t)NTOK * DDIM + row] = (float)idx;
            }
        }
        __syncthreads();
    }

    __threadfence();
    if (tid == 0) s_loss = (atomicAdd(&g_all_done, 1) == n_groups - 1);
    __syncthreads();
    if (s_loss) {
        __threadfence();
        do_loss(out, out_size, tid);
    }
}

__global__ void fill_zero_kernel(float* __restrict__ p, long long n) {
    long long i = (long long)blockIdx.x * blockDim.x + threadIdx.x;
    if (i < n) p[i] = 0.f;
}

// ---------------------------------------------------------------------------
extern "C" void kernel_launch(void* const* d_in, const int* in_sizes, int n_in,
                              void* d_out, int out_size) {
    const float* token = (const float*)d_in[0];
    const float* cb    = (const float*)d_in[1];
    if (n_in >= 2 && in_sizes[0] == KCB * DDIM && in_sizes[1] == NTOK * DDIM) {
        const float* t = token; token = cb; cb = t;
    }
    float* out = (float*)d_out;

    __half* cb_h;
    cudaGetSymbolAddress((void**)&cb_h, g_cb_h);

    cudaFuncSetAttribute(vq_main_kernel,
                         cudaFuncAttributeMaxDynamicSharedMemorySize, SMEM_TOTAL);
    cudaFuncSetAttribute(rescue_kernel,
                         cudaFuncAttributeMaxDynamicSharedMemorySize, RSMEM);

    long long osz = (long long)out_size;
    int write_indices = (osz >= (long long)NTOK * DDIM + NTOK) ? 1 : 0;

    esq_kernel<<<KCB / 8, 256>>>(cb);
    vq_main_kernel<<<NTOK / BM, NT, SMEM_TOTAL>>>(token, cb_h, cb, out,
                                                  write_indices);
    rescue_kernel<<<dim3(NGRP, RNB), 256, RSMEM>>>(token, cb, out, osz,
                                                   write_indices);

    long long expected = (long long)NTOK * DDIM + NTOK + 1;
    if (osz > expected) {
        long long tail = osz - expected;
        int blocks = (int)((tail + 255) / 256);
        fill_zero_kernel<<<blocks, 256>>>(out + expected, tail);
    }
}

// round 13
// speedup vs baseline: 1.1110x; 1.0262x over previous
#include <cuda_runtime.h>
#include <cuda_fp16.h>
#include <cstdint>

#define DDIM 768
#define KCB  2048
#define NTOK 16384
#define BM   128
#define BN   128
#define BK   32
#define NKIT (DDIM / BK)        // 24 k-iters per N-block
#define NNB  (KCB / BN)         // 16 N-blocks
#define TOTIT (NKIT * NNB)      // 384
#define MARGIN 0.20f
#define CAP 1024
#define NT 256                  // threads in vq_main (8 warps, 2x4 grid)

#define A_BYTES (NKIT * 8192)   // 196608
#define B_BYTES (4 * 8192)      // 4-stage B ring
#define SMEM_TOTAL (A_BYTES + B_BYTES)   // 229376

// rescue tiling (full-rescue fallback; expected ~0-8 rows)
#define RG  16
#define RNB 16
#define NGRP (CAP / RG)         // 64
#define XS_STRIDE 769
#define CT_STRIDE 132
#define RSMEM ((RG * XS_STRIDE + 32 * CT_STRIDE) * 4)   // 66112

// ---------------- device scratch ----------------
__device__ __half g_cb_h[KCB * DDIM];
__device__ float g_half_esq[KCB];
__device__ int   g_indices[NTOK];
__device__ float g_row_partial[NTOK];
__device__ int   g_flag_count;
__device__ int   g_flag_rows[CAP];
__device__ unsigned long long g_slot_best[CAP];
__device__ int   g_group_done[NGRP];
__device__ int   g_all_done;

// ---------------- helpers ----------------
__device__ __forceinline__ uint32_t smem_u32(const void* p) {
    uint32_t a;
    asm("{ .reg .u64 t; cvta.to.shared.u64 t, %1; cvt.u32.u64 %0, t; }"
        : "=r"(a) : "l"(p));
    return a;
}
#define CP_ASYNC16(dst, src) \
    asm volatile("cp.async.cg.shared.global [%0], [%1], 16;" :: "r"(dst), "l"(src))
#define CP_COMMIT() asm volatile("cp.async.commit_group;" ::: "memory")
#define CP_WAIT0()  asm volatile("cp.async.wait_group 0;" ::: "memory")
#define CP_WAIT2()  asm volatile("cp.async.wait_group 2;" ::: "memory")

__device__ __forceinline__ int swz16(int r, int c) {
    return (r >> 1) * 8 + ((((r & 1) << 2) | c) ^ ((r >> 1) & 7));
}
__device__ __forceinline__ void ldsm4(uint32_t* r, uint32_t addr) {
    asm volatile("ldmatrix.sync.aligned.m8n8.x4.shared.b16 {%0,%1,%2,%3}, [%4];"
                 : "=r"(r[0]), "=r"(r[1]), "=r"(r[2]), "=r"(r[3]) : "r"(addr));
}
__device__ __forceinline__ void mma16816(float* d, const uint32_t* a,
                                         uint32_t b0, uint32_t b1) {
    asm volatile(
        "mma.sync.aligned.m16n8k16.row.col.f32.f16.f16.f32 "
        "{%0,%1,%2,%3},{%4,%5,%6,%7},{%8,%9},{%0,%1,%2,%3};"
        : "+f"(d[0]), "+f"(d[1]), "+f"(d[2]), "+f"(d[3])
        : "r"(a[0]), "r"(a[1]), "r"(a[2]), "r"(a[3]), "r"(b0), "r"(b1));
}
// top-3 insert with index tracking for #1/#2 (lowest-index tie priority)
__device__ __forceinline__ void insert3(float& b1, int& i1, float& b2, int& i2,
                                        float& b3, float v, int ix) {
    if (v > b1 || (v == b1 && ix < i1)) {
        b3 = b2; b2 = b1; i2 = i1; b1 = v; i1 = ix;
    } else if (v > b2 || (v == b2 && ix < i2)) {
        b3 = b2; b2 = v; i2 = ix;
    } else if (v > b3) {
        b3 = v;
    }
}
// pack (score, idx) so u64-max == (higher score, then LOWER idx)
__device__ __forceinline__ unsigned long long pack_si(float v, int idx) {
    uint32_t b = __float_as_uint(v);
    b = (b & 0x80000000u) ? ~b : (b | 0x80000000u);
    return ((unsigned long long)b << 32) | (unsigned)(0xFFFFFFFFu - (unsigned)idx);
}

__device__ __forceinline__ void load_frags(
    uint32_t (&af)[4][4], uint32_t (&bf)[2][4],
    uint32_t Ab, uint32_t Bb, int c0,
    int warp_m, int warp_n, int a_r, int a_c, int b_r, int b_c)
{
    #pragma unroll
    for (int mt = 0; mt < 4; ++mt)
        ldsm4(af[mt], Ab + swz16(warp_m * 64 + mt * 16 + a_r, c0 + a_c) * 16);
    #pragma unroll
    for (int np = 0; np < 2; ++np)
        ldsm4(bf[np], Bb + swz16(warp_n * 32 + np * 16 + b_r, c0 + b_c) * 16);
}

// convert one 16B chunk (8 fp32 -> 8 fp16) into swizzled smA
__device__ __forceinline__ void conv_chunk(char* smA, const float* tokf,
                                           int rowBase, int stage, int within)
{
    int r = within >> 2, c2 = within & 3;
    const float* src = tokf + (size_t)(rowBase + r) * DDIM + stage * BK + c2 * 8;
    float4 a = *(const float4*)(src);
    float4 b = *(const float4*)(src + 4);
    __half2 h0 = __floats2half2_rn(a.x, a.y);
    __half2 h1 = __floats2half2_rn(a.z, a.w);
    __half2 h2 = __floats2half2_rn(b.x, b.y);
    __half2 h3 = __floats2half2_rn(b.z, b.w);
    uint4 o{*(uint32_t*)&h0, *(uint32_t*)&h1, *(uint32_t*)&h2, *(uint32_t*)&h3};
    *(uint4*)(smA + stage * 8192 + swz16(r, c2) * 16) = o;
}

// ---------------------------------------------------------------------------
// esq: warp-per-row (8 rows/block), codebook fp16 conversion + counter resets
// ---------------------------------------------------------------------------
__global__ __launch_bounds__(256) void esq_kernel(const float* __restrict__ cbp) {
    const int tid = threadIdx.x;
    if (blockIdx.x == 0) {
        if (tid < NGRP) g_group_done[tid] = 0;
        if (tid == 0) { g_flag_count = 0; g_all_done = 0; }
    }
    const int warp = tid >> 5, lane = tid & 31;
    const int k = blockIdx.x * 8 + warp;
    const float4* row = (const float4*)(cbp + (size_t)k * DDIM);
    uint2* dst = (uint2*)(g_cb_h + (size_t)k * DDIM);
    float s = 0.f;
    #pragma unroll
    for (int j = 0; j < 6; ++j) {
        const int q = lane + j * 32;
        float4 v = row[q];
        s += v.x * v.x + v.y * v.y + v.z * v.z + v.w * v.w;
        __half2 h0 = __floats2half2_rn(v.x, v.y);
        __half2 h1 = __floats2half2_rn(v.z, v.w);
        uint2 o{*(uint32_t*)&h0, *(uint32_t*)&h1};
        dst[q] = o;
    }
    #pragma unroll
    for (int off = 16; off > 0; off >>= 1) s += __shfl_down_sync(0xFFFFFFFFu, s, off);
    if (lane == 0) g_half_esq[k] = 0.5f * s;
}

// ---------------------------------------------------------------------------
// Main fp16 mma.sync GEMM + top-3 argmax + candidate re-scoring + epilogue.
// ---------------------------------------------------------------------------
__global__ __launch_bounds__(NT, 1) void vq_main_kernel(
    const float* __restrict__ tokf, const __half* __restrict__ cbh,
    const float* __restrict__ cbf, float* __restrict__ outp, int write_indices)
{
    extern __shared__ char sm[];
    char* smA = sm;
    char* smB = sm + A_BYTES;

    const int tid = threadIdx.x;
    const int lane = tid & 31;
    const int wid = tid >> 5;
    const int warp_m = wid & 1;
    const int warp_n = wid >> 1;
    const int rowBase = blockIdx.x * BM;

    const uint32_t smA32 = smem_u32(smA);
    const uint32_t smB32 = smem_u32(smB);

    const int ld_r0 = tid >> 2, ld_c0 = tid & 3;
    const int ld_r1 = ld_r0 + 64;

    CP_ASYNC16(smB32 + swz16(ld_r0, ld_c0) * 16,
               cbh + (size_t)ld_r0 * DDIM + ld_c0 * 8);
    CP_ASYNC16(smB32 + swz16(ld_r1, ld_c0) * 16,
               cbh + (size_t)ld_r1 * DDIM + ld_c0 * 8);
    CP_COMMIT();
    CP_ASYNC16(smB32 + 8192 + swz16(ld_r0, ld_c0) * 16,
               cbh + (size_t)ld_r0 * DDIM + BK + ld_c0 * 8);
    CP_ASYNC16(smB32 + 8192 + swz16(ld_r1, ld_c0) * 16,
               cbh + (size_t)ld_r1 * DDIM + BK + ld_c0 * 8);
    CP_COMMIT();

    // Prologue: convert only stages 0..3 (rest overlapped in-loop)
    #pragma unroll 4
    for (int j = 0; j < 8; ++j) {
        int idx = tid + j * NT;            // 0..2047 chunks (stages 0-3)
        conv_chunk(smA, tokf, rowBase, idx >> 9, idx & 511);
    }

    float acc[4][4][4];
    #pragma unroll
    for (int mt = 0; mt < 4; ++mt)
        #pragma unroll
        for (int nt = 0; nt < 4; ++nt)
            #pragma unroll
            for (int e = 0; e < 4; ++e) acc[mt][nt][e] = 0.f;

    float tb1[8], tb2[8], tb3[8]; int ti1[8], ti2[8];
    #pragma unroll
    for (int s = 0; s < 8; ++s) {
        tb1[s] = -3.4e38f; tb2[s] = -3.4e38f; tb3[s] = -3.4e38f;
        ti1[s] = 0x7FFFFFFF; ti2[s] = 0x7FFFFFFF;
    }

    const int a_r = (lane & 15);
    const int a_c = (lane >> 4);
    const int b_r = ((lane >> 4) << 3) + (lane & 7);
    const int b_c = ((lane >> 3) & 1);

    uint32_t af[2][4][4];
    uint32_t bf[2][2][4];

    for (int ss = 0; ss < TOTIT / 2; ++ss) {
        __syncthreads();

        const int st0 = 2 * ss + 2;
        if (st0 < TOTIT) {
            #pragma unroll
            for (int j = 0; j < 2; ++j) {
                int st = st0 + j;
                int nb = st / NKIT, it = st % NKIT;
                const __half* base = cbh + (size_t)(nb * BN) * DDIM + it * BK + ld_c0 * 8;
                uint32_t dst = smB32 + (st & 3) * 8192;
                CP_ASYNC16(dst + swz16(ld_r0, ld_c0) * 16, base + (size_t)ld_r0 * DDIM);
                CP_ASYNC16(dst + swz16(ld_r1, ld_c0) * 16, base + (size_t)ld_r1 * DDIM);
                CP_COMMIT();
            }
            CP_WAIT2();
        } else {
            CP_WAIT0();
        }

        const int g0 = 2 * ss;
        const uint32_t Ab0 = smA32 + (g0 % NKIT) * 8192;
        const uint32_t Ab1 = smA32 + ((g0 + 1) % NKIT) * 8192;
        const uint32_t Bb0 = smB32 + (g0 & 3) * 8192;
        const uint32_t Bb1 = smB32 + ((g0 + 1) & 3) * 8192;

        load_frags(af[0], bf[0], Ab0, Bb0, 0, warp_m, warp_n, a_r, a_c, b_r, b_c);
        #pragma unroll
        for (int p = 0; p < 4; ++p) {
            const int cur = p & 1, nxt = cur ^ 1;
            if (p < 3) {
                const int pn = p + 1;
                load_frags(af[nxt], bf[nxt],
                           (pn >> 1) ? Ab1 : Ab0, (pn >> 1) ? Bb1 : Bb0,
                           (pn & 1) * 2, warp_m, warp_n, a_r, a_c, b_r, b_c);
            }
            #pragma unroll
            for (int mt = 0; mt < 4; ++mt)
                #pragma unroll
                for (int nt = 0; nt < 4; ++nt)
                    mma16816(acc[mt][nt], af[cur][mt],
                             bf[cur][nt >> 1][(nt & 1) * 2],
                             bf[cur][nt >> 1][(nt & 1) * 2 + 1]);
        }

        // overlapped A-conversion: stages 4..23, 4 per superstep (ss 0..4)
        if (ss < 5) {
            const int cstage = 4 + ss * 4;
            #pragma unroll
            for (int cj = 0; cj < 4; ++cj) {
                int stg = cstage + cj;
                conv_chunk(smA, tokf, rowBase, stg, tid);
                conv_chunk(smA, tokf, rowBase, stg, tid + 256);
            }
        }

        if (((g0 + 1) % NKIT) == NKIT - 1) {
            const int nbase = ((g0 + 1) / NKIT) * BN + warp_n * 32;
            #pragma unroll
            for (int mt = 0; mt < 4; ++mt) {
                #pragma unroll
                for (int nt = 0; nt < 4; ++nt) {
                    const int col0 = nbase + nt * 8 + (lane & 3) * 2;
                    const float he0 = __ldg(&g_half_esq[col0]);
                    const float he1 = __ldg(&g_half_esq[col0 + 1]);
                    const int s_lo = mt * 2, s_hi = mt * 2 + 1;
                    insert3(tb1[s_lo], ti1[s_lo], tb2[s_lo], ti2[s_lo], tb3[s_lo],
                            acc[mt][nt][0] - he0, col0);
                    insert3(tb1[s_lo], ti1[s_lo], tb2[s_lo], ti2[s_lo], tb3[s_lo],
                            acc[mt][nt][1] - he1, col0 + 1);
                    insert3(tb1[s_hi], ti1[s_hi], tb2[s_hi], ti2[s_hi], tb3[s_hi],
                            acc[mt][nt][2] - he0, col0);
                    insert3(tb1[s_hi], ti1[s_hi], tb2[s_hi], ti2[s_hi], tb3[s_hi],
                            acc[mt][nt][3] - he1, col0 + 1);
                    acc[mt][nt][0] = 0.f; acc[mt][nt][1] = 0.f;
                    acc[mt][nt][2] = 0.f; acc[mt][nt][3] = 0.f;
                }
            }
        }
    }

    // cross-lane reduce over the 4 lanes (lane&3) sharing each row
    #pragma unroll
    for (int s = 0; s < 8; ++s) {
        #pragma unroll
        for (int d = 1; d <= 2; d <<= 1) {
            float ob1 = __shfl_xor_sync(0xFFFFFFFFu, tb1[s], d);
            int   oi1 = __shfl_xor_sync(0xFFFFFFFFu, ti1[s], d);
            float ob2 = __shfl_xor_sync(0xFFFFFFFFu, tb2[s], d);
            int   oi2 = __shfl_xor_sync(0xFFFFFFFFu, ti2[s], d);
            float ob3 = __shfl_xor_sync(0xFFFFFFFFu, tb3[s], d);
            insert3(tb1[s], ti1[s], tb2[s], ti2[s], tb3[s], ob1, oi1);
            insert3(tb1[s], ti1[s], tb2[s], ti2[s], tb3[s], ob2, oi2);
            insert3(tb1[s], ti1[s], tb2[s], ti2[s], tb3[s], ob3, 0x7FFFFFFF);
        }
    }

    __syncthreads();
    // post-loop smem layout (inside B ring, mainloop done)
    float* rv1 = (float*)smB;                    // [128][4]
    int*   ri1 = (int*)(smB + 2048);
    float* rv2 = (float*)(smB + 4096);
    int*   ri2 = (int*)(smB + 6144);
    float* rv3 = (float*)(smB + 8192);
    int*   sidx = (int*)(smB + 10240);           // [128]
    int*   pcnt = (int*)(smB + 10752);
    int*   pend_row = (int*)(smB + 11264);       // [128]
    int*   pend_nc  = (int*)(smB + 11776);       // [128]
    int*   pend_cand = (int*)(smB + 12288);      // [128][8]
    if (tid == 0) *pcnt = 0;
    if ((lane & 3) == 0) {
        #pragma unroll
        for (int s = 0; s < 8; ++s) {
            int rowl = warp_m * 64 + (s >> 1) * 16 + ((s & 1) << 3) + (lane >> 2);
            rv1[rowl * 4 + warp_n] = tb1[s];
            ri1[rowl * 4 + warp_n] = ti1[s];
            rv2[rowl * 4 + warp_n] = tb2[s];
            ri2[rowl * 4 + warp_n] = ti2[s];
            rv3[rowl * 4 + warp_n] = tb3[s];
        }
    }
    __syncthreads();
    if (tid < BM) {
        float g1[4], g2[4], g3[4]; int gi1[4], gi2[4];
        #pragma unroll
        for (int w = 0; w < 4; ++w) {
            g1[w] = rv1[tid * 4 + w]; gi1[w] = ri1[tid * 4 + w];
            g2[w] = rv2[tid * 4 + w]; gi2[w] = ri2[tid * 4 + w];
            g3[w] = rv3[tid * 4 + w];
        }
        float b1 = g1[0]; int i1 = gi1[0];
        #pragma unroll
        for (int w = 1; w < 4; ++w)
            if (g1[w] > b1 || (g1[w] == b1 && gi1[w] < i1)) { b1 = g1[w]; i1 = gi1[w]; }
        const float thr = b1 - MARGIN;
        bool full = false;
        int nc = 0; int cd[8];
        #pragma unroll
        for (int w = 0; w < 4; ++w) {
            if (g3[w] >= thr) full = true;
            if (g1[w] >= thr) cd[nc++] = gi1[w];
            if (g2[w] >= thr) cd[nc++] = gi2[w];
        }
        if (full) {
            int p = atomicAdd(&g_flag_count, 1);
            if (p < CAP) { g_flag_rows[p] = rowBase + tid; g_slot_best[p] = 0ull; }
        } else if (nc > 1) {
            int p = atomicAdd(pcnt, 1);
            pend_row[p] = tid; pend_nc[p] = nc;
            #pragma unroll
            for (int c = 0; c < 8; ++c)
                if (c < nc) pend_cand[p * 8 + c] = cd[c];
        }
        g_indices[rowBase + tid] = i1;
        sidx[tid] = i1;
    }
    __syncthreads();

    // exact fp32 re-scoring of multi-candidate rows (warp per pending row)
    {
        const int P = *pcnt;
        for (int pi = wid; pi < P; pi += 8) {
            const int rl = pend_row[pi];
            const int nc = pend_nc[pi];
            const float* xrow = tokf + (size_t)(rowBase + rl) * DDIM;
            float4 xr[6];
            #pragma unroll
            for (int j = 0; j < 6; ++j)
                xr[j] = *(const float4*)(xrow + (j * 32 + lane) * 4);
            float best = -3.4e38f; int bidx = 0x7FFFFFFF;
            for (int c = 0; c < nc; ++c) {
                const int ci = pend_cand[pi * 8 + c];
                const float* erow = cbf + (size_t)ci * DDIM;
                float s = 0.f;
                #pragma unroll
                for (int j = 0; j < 6; ++j) {
                    float4 e = *(const float4*)(erow + (j * 32 + lane) * 4);
                    s += xr[j].x * e.x + xr[j].y * e.y + xr[j].z * e.z + xr[j].w * e.w;
                }
                #pragma unroll
                for (int off = 16; off > 0; off >>= 1)
                    s += __shfl_down_sync(0xFFFFFFFFu, s, off);
                if (lane == 0) {
                    float sc = s - g_half_esq[ci];
                    if (sc > best || (sc == best && ci < bidx)) { best = sc; bidx = ci; }
                }
            }
            if (lane == 0) {
                sidx[rl] = bidx;
                g_indices[rowBase + rl] = bidx;
            }
        }
    }
    __syncthreads();

    // fused gather + loss-partial epilogue: x read from resident fp16 A tile
    for (int rr = wid * 16; rr < wid * 16 + 16; ++rr) {
        const int idx = sidx[rr];
        const int grow = rowBase + rr;
        const float* qrow = cbf + (size_t)idx * DDIM;
        float* orow = outp + (size_t)grow * DDIM;
        float s = 0.f;
        #pragma unroll
        for (int jj = 0; jj < 3; ++jj) {
            const int ch = lane + jj * 32;          // chunk 0..95
            const int stage = ch >> 2, c2 = ch & 3;
            const int d0 = ch * 8;
            float4 q0 = *(const float4*)(qrow + d0);
            float4 q1 = *(const float4*)(qrow + d0 + 4);
            uint4 xv = *(const uint4*)(smA + stage * 8192 + swz16(rr, c2) * 16);
            float2 x0 = __half22float2(*(__half2*)&xv.x);
            float2 x1 = __half22float2(*(__half2*)&xv.y);
            float2 x2 = __half22float2(*(__half2*)&xv.z);
            float2 x3 = __half22float2(*(__half2*)&xv.w);
            *(float4*)(orow + d0) = q0;
            *(float4*)(orow + d0 + 4) = q1;
            float d;
            d = q0.x - x0.x; s += d * d;
            d = q0.y - x0.y; s += d * d;
            d = q0.z - x1.x; s += d * d;
            d = q0.w - x1.y; s += d * d;
            d = q1.x - x2.x; s += d * d;
            d = q1.y - x2.y; s += d * d;
            d = q1.z - x3.x; s += d * d;
            d = q1.w - x3.y; s += d * d;
        }
        #pragma unroll
        for (int off = 16; off > 0; off >>= 1)
            s += __shfl_down_sync(0xFFFFFFFFu, s, off);
        if (lane == 0) {
            g_row_partial[grow] = s;
            if (write_indices) outp[(size_t)NTOK * DDIM + grow] = (float)idx;
        }
    }
}

// ---------------------------------------------------------------------------
// Full rescue + fixup + loss (safety net; expected ~0-8 rows)
// ---------------------------------------------------------------------------
__device__ __forceinline__ void do_loss(float* __restrict__ out,
                                        long long out_size, int tid) {
    __shared__ float lsm[256];
    const float4* rp = (const float4*)g_row_partial;
    float s = 0.f;
    #pragma unroll
    for (int j = 0; j < 16; ++j) {
        float4 v = rp[tid + j * 256];
        s += v.x + v.y + v.z + v.w;
    }
    lsm[tid] = s;
    __syncthreads();
    for (int off = 128; off > 0; off >>= 1) {
        if (tid < off) lsm[tid] += lsm[tid + off];
        __syncthreads();
    }
    if (tid == 0) {
        long long pos = (long long)NTOK * DDIM + NTOK;
        if (out_size > pos) out[pos] = lsm[0] / (float)((long long)NTOK * DDIM);
    }
}

__global__ __launch_bounds__(256) void rescue_kernel(
    const float* __restrict__ token, const float* __restrict__ cbp,
    float* __restrict__ out, long long out_size, int write_indices)
{
    const int tid = threadIdx.x;
    int cnt = g_flag_count; if (cnt > CAP) cnt = CAP;
    const int rg = blockIdx.x;
    const int nb = blockIdx.y;

    if (cnt == 0) {
        if (rg == 0 && nb == 0) do_loss(out, out_size, tid);
        return;
    }
    if (rg * RG >= cnt) return;
    const int n_groups = (cnt + RG - 1) / RG;

    extern __shared__ float rsm[];
    float* xs = rsm;
    float* ct = rsm + RG * XS_STRIDE;
    __shared__ float rv[256];
    __shared__ int   ri[256];
    __shared__ int   s_last, s_loss;

    const int tr = tid & 15;
    const int tc = tid >> 4;

    {
        int slot = rg * RG + tr;
        int grow = (slot < cnt) ? g_flag_rows[slot] : 0;
        const float* src = token + (size_t)grow * DDIM;
        #pragma unroll
        for (int j = 0; j < 12; ++j) {
            int q = tc + j * 16;
            float4 v = *(const float4*)(src + q * 4);
            float* dst = xs + tr * XS_STRIDE + q * 4;
            dst[0] = v.x; dst[1] = v.y; dst[2] = v.z; dst[3] = v.w;
        }
    }

    float acc[8];
    #pragma unroll
    for (int j = 0; j < 8; ++j) acc[j] = 0.f;

    for (int kt = 0; kt < NKIT; ++kt) {
        __syncthreads();
        #pragma unroll
        for (int j = 0; j < 4; ++j) {
            int idx = tid + j * 256;
            int code = idx >> 3, q = idx & 7;
            float4 v = *(const float4*)(cbp + (size_t)(nb * 128 + code) * DDIM
                                        + kt * 32 + q * 4);
            ct[(q * 4 + 0) * CT_STRIDE + code] = v.x;
            ct[(q * 4 + 1) * CT_STRIDE + code] = v.y;
            ct[(q * 4 + 2) * CT_STRIDE + code] = v.z;
            ct[(q * 4 + 3) * CT_STRIDE + code] = v.w;
        }
        __syncthreads();
        #pragma unroll 4
        for (int kk = 0; kk < 32; ++kk) {
            float xv = xs[tr * XS_STRIDE + kt * 32 + kk];
            const float4 ca = *(const float4*)(ct + kk * CT_STRIDE + tc * 8);
            const float4 cb4 = *(const float4*)(ct + kk * CT_STRIDE + tc * 8 + 4);
            acc[0] += xv * ca.x; acc[1] += xv * ca.y;
            acc[2] += xv * ca.z; acc[3] += xv * ca.w;
            acc[4] += xv * cb4.x; acc[5] += xv * cb4.y;
            acc[6] += xv * cb4.z; acc[7] += xv * cb4.w;
        }
    }

    float bv = -3.4e38f; int bi = 0;
    #pragma unroll
    for (int j = 0; j < 8; ++j) {
        int code = nb * 128 + tc * 8 + j;
        float sc = acc[j] - g_half_esq[code];
        if (sc > bv) { bv = sc; bi = code; }
    }
    rv[tc * 16 + tr] = bv; ri[tc * 16 + tr] = bi;
    __syncthreads();
    if (tid < 16) {
        float b = rv[tid]; int i = ri[tid];
        #pragma unroll
        for (int c = 1; c < 16; ++c) {
            float v = rv[c * 16 + tid]; int ix = ri[c * 16 + tid];
            if (v > b || (v == b && ix < i)) { b = v; i = ix; }
        }
        int slot = rg * RG + tid;
        if (slot < cnt) atomicMax(&g_slot_best[slot], pack_si(b, i));
    }
    __threadfence();
    __syncthreads();
    if (tid == 0) s_last = (atomicAdd(&g_group_done[rg], 1) == RNB - 1);
    __syncthreads();
    if (!s_last) return;

    __threadfence();
    __shared__ int f_row, f_idx, f_go;
    __shared__ float ws[8];
    const int slot_end = min(rg * RG + RG, cnt);
    for (int slot = rg * RG; slot < slot_end; ++slot) {
        if (tid == 0) {
            unsigned long long p = g_slot_best[slot];
            int bi2 = (int)(0xFFFFFFFFu - (unsigned)(p & 0xFFFFFFFFu));
            int row = g_flag_rows[slot];
            f_row = row; f_idx = bi2;
            f_go = (g_indices[row] != bi2);
            if (f_go) g_indices[row] = bi2;
        }
        __syncthreads();
        if (f_go) {
            const int row = f_row, idx = f_idx;
            float s = 0.f;
            if (tid < 192) {
                float4 q = *(const float4*)(cbp + (size_t)idx * DDIM + tid * 4);
                float4 x = *(const float4*)(token + (size_t)row * DDIM + tid * 4);
                *(float4*)(out + (size_t)row * DDIM + tid * 4) = q;
                float dx = q.x - x.x, dy = q.y - x.y, dz = q.z - x.z, dw = q.w - x.w;
                s = dx * dx + dy * dy + dz * dz + dw * dw;
            }
            #pragma unroll
            for (int off = 16; off > 0; off >>= 1)
                s += __shfl_down_sync(0xFFFFFFFFu, s, off);
            if ((tid & 31) == 0) ws[tid >> 5] = s;
            __syncthreads();
            if (tid == 0) {
                float tt = 0.f;
                #pragma unroll
                for (int w = 0; w < 8; w++) tt += ws[w];
                g_row_partial[row] = tt;
                if (write_indices) out[(size_t)NTOK * DDIM + row] = (float)idx;
            }
        }
        __syncthreads();
    }

    __threadfence();
    if (tid == 0) s_loss = (atomicAdd(&g_all_done, 1) == n_groups - 1);
    __syncthreads();
    if (s_loss) {
        __threadfence();
        do_loss(out, out_size, tid);
    }
}

__global__ void fill_zero_kernel(float* __restrict__ p, long long n) {
    long long i = (long long)blockIdx.x * blockDim.x + threadIdx.x;
    if (i < n) p[i] = 0.f;
}

// ---------------------------------------------------------------------------
extern "C" void kernel_launch(void* const* d_in, const int* in_sizes, int n_in,
                              void* d_out, int out_size) {
    const float* token = (const float*)d_in[0];
    const float* cb    = (const float*)d_in[1];
    if (n_in >= 2 && in_sizes[0] == KCB * DDIM && in_sizes[1] == NTOK * DDIM) {
        const float* t = token; token = cb; cb = t;
    }
    float* out = (float*)d_out;

    __half* cb_h;
    cudaGetSymbolAddress((void**)&cb_h, g_cb_h);

    cudaFuncSetAttribute(vq_main_kernel,
                         cudaFuncAttributeMaxDynamicSharedMemorySize, SMEM_TOTAL);
    cudaFuncSetAttribute(rescue_kernel,
                         cudaFuncAttributeMaxDynamicSharedMemorySize, RSMEM);

    long long osz = (long long)out_size;
    int write_indices = (osz >= (long long)NTOK * DDIM + NTOK) ? 1 : 0;

    esq_kernel<<<KCB / 8, 256>>>(cb);
    vq_main_kernel<<<NTOK / BM, NT, SMEM_TOTAL>>>(token, cb_h, cb, out,
                                                  write_indices);
    rescue_kernel<<<dim3(NGRP, RNB), 256, RSMEM>>>(token, cb, out, osz,
                                                   write_indices);

    long long expected = (long long)NTOK * DDIM + NTOK + 1;
    if (osz > expected) {
        long long tail = osz - expected;
        int blocks = (int)((tail + 255) / 256);
        fill_zero_kernel<<<blocks, 256>>>(out + expected, tail);
    }
}